// round 1
// baseline (speedup 1.0000x reference)
#include <cuda_runtime.h>
#include <math.h>

#define B_   8
#define N_   1024
#define DM   512
#define H_   8
#define DH   64
#define QKVD 1536
#define NS_  1
#define SCALE 0.125f

// ---------------- scratch (device globals; no allocations) ----------------
__device__ float g_qkv[(size_t)B_ * N_ * QKVD];        //  50.3 MB  [b][n][3D]
__device__ float g_bias[(size_t)B_ * H_ * N_ * N_];    // 268.4 MB  [b][h][i][j] (alpha pre-folded)
__device__ float g_att[(size_t)B_ * N_ * DM];          //  16.8 MB  [b][n][h*64+d]

// =====================================================================
// Generic tiled SGEMM body:  C[M][Nc] = A[M][K] @ W[Nc][K]^T (+ bias)
// 64x64 tile, 256 threads, 4x4 per thread, K-chunks of 16.
// =====================================================================
__device__ __forceinline__ void sgemm_body(
    const float* __restrict__ A, const float* __restrict__ W,
    const float* __restrict__ bias, float* __restrict__ C,
    int Nc, int K)
{
    __shared__ float As[16][68];   // [k][m]  (transposed)
    __shared__ float Bs[16][68];   // [k][n]  (transposed)

    const int tid = threadIdx.x;
    const int tx = tid & 15, ty = tid >> 4;
    const int m0 = blockIdx.y * 64, n0 = blockIdx.x * 64;

    float acc[4][4] = {};

    for (int k0 = 0; k0 < K; k0 += 16) {
        // fill: 64x16 tile each, one float4 per thread
        {
            int row = tid >> 2;
            int kk4 = (tid & 3) << 2;
            float4 a = *(const float4*)&A[(size_t)(m0 + row) * K + k0 + kk4];
            As[kk4 + 0][row] = a.x; As[kk4 + 1][row] = a.y;
            As[kk4 + 2][row] = a.z; As[kk4 + 3][row] = a.w;
            float4 w = *(const float4*)&W[(size_t)(n0 + row) * K + k0 + kk4];
            Bs[kk4 + 0][row] = w.x; Bs[kk4 + 1][row] = w.y;
            Bs[kk4 + 2][row] = w.z; Bs[kk4 + 3][row] = w.w;
        }
        __syncthreads();

        #pragma unroll
        for (int kk = 0; kk < 16; kk++) {
            float4 a  = *(const float4*)&As[kk][ty << 2];
            float4 bb = *(const float4*)&Bs[kk][tx << 2];
            float av[4] = {a.x, a.y, a.z, a.w};
            float bv[4] = {bb.x, bb.y, bb.z, bb.w};
            #pragma unroll
            for (int r = 0; r < 4; r++)
                #pragma unroll
                for (int c = 0; c < 4; c++)
                    acc[r][c] = fmaf(av[r], bv[c], acc[r][c]);
        }
        __syncthreads();
    }

    // epilogue
    float4 bvec = make_float4(0.f, 0.f, 0.f, 0.f);
    if (bias) bvec = *(const float4*)&bias[n0 + (tx << 2)];
    #pragma unroll
    for (int r = 0; r < 4; r++) {
        int m = m0 + (ty << 2) + r;
        float4 out = make_float4(acc[r][0] + bvec.x, acc[r][1] + bvec.y,
                                 acc[r][2] + bvec.z, acc[r][3] + bvec.w);
        *(float4*)&C[(size_t)m * Nc + n0 + (tx << 2)] = out;
    }
}

__global__ void __launch_bounds__(256)
k_gemm_qkv(const float* __restrict__ A, const float* __restrict__ W)
{
    sgemm_body(A, W, nullptr, g_qkv, QKVD, DM);
}

__global__ void __launch_bounds__(256)
k_gemm_out(const float* __restrict__ W, const float* __restrict__ bias,
           float* __restrict__ C)
{
    sgemm_body(g_att, W, bias, C, DM, DM);
}

// =====================================================================
// Pairwise bias MLP:  per (b,i,j) -> 8 head biases (alpha folded in).
// block = (32 j, 8 i); one thread per pair.
// =====================================================================
__global__ void __launch_bounds__(256)
k_bias(const float* __restrict__ coords, const float* __restrict__ cs,
       const float* __restrict__ w1, const float* __restrict__ b1,
       const float* __restrict__ w2, const float* __restrict__ b2,
       const float* __restrict__ alpha_p)
{
    __shared__ float sw1[32][4];
    __shared__ float sb1[32];
    __shared__ float sw2[8][32];
    __shared__ float sb2[8];
    __shared__ float ssc[3];
    __shared__ float salpha;

    const int tid = threadIdx.y * 32 + threadIdx.x;
    if (tid < 128) ((float*)sw1)[tid] = w1[tid];
    if (tid < 256) ((float*)sw2)[tid] = w2[tid];
    if (tid < 32)  sb1[tid] = b1[tid];
    if (tid < 8)   sb2[tid] = b2[tid];
    if (tid < 3)   ssc[tid] = cs[tid];
    if (tid == 0)  salpha = alpha_p[0];
    __syncthreads();

    const int b = blockIdx.z;
    const int i = blockIdx.y * 8 + threadIdx.y;
    const int j = blockIdx.x * 32 + threadIdx.x;

    float out[8];
    #pragma unroll
    for (int h = 0; h < 8; h++) out[h] = 0.f;

    if (i >= NS_ && j >= NS_) {
        const float* ci = &coords[((size_t)b * N_ + i) * 3];
        const float* cj = &coords[((size_t)b * N_ + j) * 3];
        float dx = (ci[0] - cj[0]) / ssc[0];
        float dy = (ci[1] - cj[1]) / ssc[1];
        float dz = (ci[2] - cj[2]) / ssc[2];
        float dist = sqrtf(dx * dx + dy * dy + dz * dz);

        #pragma unroll
        for (int h = 0; h < 8; h++) out[h] = sb2[h];

        #pragma unroll 8
        for (int k = 0; k < 32; k++) {
            float t = fmaf(sw1[k][0], dx,
                      fmaf(sw1[k][1], dy,
                      fmaf(sw1[k][2], dz,
                      fmaf(sw1[k][3], dist, sb1[k]))));
            float g = 0.5f * t * (1.0f + erff(t * 0.70710678118654752f));
            #pragma unroll
            for (int h = 0; h < 8; h++)
                out[h] = fmaf(sw2[h][k], g, out[h]);
        }
    }

    const size_t base = ((size_t)b * H_ * N_ + i) * N_ + j;  // h stride = N_*N_
    #pragma unroll
    for (int h = 0; h < 8; h++)
        g_bias[base + (size_t)h * N_ * N_] = salpha * out[h];
}

// =====================================================================
// Flash attention per (b, h, 64-row i-tile).  256 threads, 4x4/thread.
// qs/ks transposed [d][row] for conflict-free float4 operand reads;
// vs natural [j][d]; ps natural [i][j] (broadcast reads in PV).
// =====================================================================
#define ATTN_SMEM ((4 * 64 * 68 + 64) * 4)

__global__ void __launch_bounds__(256)
k_attn(const unsigned char* __restrict__ mask)
{
    extern __shared__ float sm[];
    float (*qs)[68] = (float(*)[68])(sm);                 // [d][i]
    float (*ks)[68] = (float(*)[68])(sm + 64 * 68);       // [d][j]
    float (*vs)[68] = (float(*)[68])(sm + 2 * 64 * 68);   // [j][d]
    float (*ps)[68] = (float(*)[68])(sm + 3 * 64 * 68);   // [i][j]
    float* madd     = sm + 4 * 64 * 68;                    // [j]

    const int b = blockIdx.z, h = blockIdx.y;
    const int i0 = blockIdx.x * 64;
    const int tid = threadIdx.x;
    const int tx = tid & 15, ty = tid >> 4;

    // load Q tile transposed
    #pragma unroll
    for (int t = 0; t < 4; t++) {
        int lin = tid + t * 256;
        int row = lin >> 4;
        int d4  = (lin & 15) << 2;
        float4 v = *(const float4*)&g_qkv[((size_t)(b * N_ + i0 + row)) * QKVD + h * DH + d4];
        qs[d4 + 0][row] = v.x; qs[d4 + 1][row] = v.y;
        qs[d4 + 2][row] = v.z; qs[d4 + 3][row] = v.w;
    }

    float m_i[4], l_i[4], o[4][4];
    #pragma unroll
    for (int r = 0; r < 4; r++) {
        m_i[r] = -INFINITY; l_i[r] = 0.f;
        #pragma unroll
        for (int c = 0; c < 4; c++) o[r][c] = 0.f;
    }

    const size_t brow = (size_t)(b * H_ + h) * N_;

    for (int j0 = 0; j0 < N_; j0 += 64) {
        __syncthreads();   // protect ks/vs/ps (and qs on iter 0) before rewrite

        // fill K (transposed) and V (natural)
        #pragma unroll
        for (int t = 0; t < 4; t++) {
            int lin = tid + t * 256;
            int row = lin >> 4;
            int d4  = (lin & 15) << 2;
            size_t rb = ((size_t)(b * N_ + j0 + row)) * QKVD + h * DH + d4;
            float4 kv = *(const float4*)&g_qkv[rb + DM];
            ks[d4 + 0][row] = kv.x; ks[d4 + 1][row] = kv.y;
            ks[d4 + 2][row] = kv.z; ks[d4 + 3][row] = kv.w;
            float4 vv = *(const float4*)&g_qkv[rb + 2 * DM];
            *(float4*)&vs[row][d4] = vv;
        }
        if (tid < 64)
            madd[tid] = mask[(size_t)b * N_ + j0 + tid] ? -1e30f : 0.0f;
        __syncthreads();

        // S = Q K^T
        float s[4][4] = {};
        #pragma unroll 16
        for (int kk = 0; kk < 64; kk++) {
            float4 a  = *(const float4*)&qs[kk][ty << 2];
            float4 bb = *(const float4*)&ks[kk][tx << 2];
            float av[4] = {a.x, a.y, a.z, a.w};
            float bv[4] = {bb.x, bb.y, bb.z, bb.w};
            #pragma unroll
            for (int r = 0; r < 4; r++)
                #pragma unroll
                for (int c = 0; c < 4; c++)
                    s[r][c] = fmaf(av[r], bv[c], s[r][c]);
        }

        // scale + bias + padding mask, then online softmax
        #pragma unroll
        for (int r = 0; r < 4; r++) {
            float4 bv = *(const float4*)&g_bias[(brow + i0 + (ty << 2) + r) * N_ + j0 + (tx << 2)];
            s[r][0] = fmaf(s[r][0], SCALE, bv.x) + madd[(tx << 2) + 0];
            s[r][1] = fmaf(s[r][1], SCALE, bv.y) + madd[(tx << 2) + 1];
            s[r][2] = fmaf(s[r][2], SCALE, bv.z) + madd[(tx << 2) + 2];
            s[r][3] = fmaf(s[r][3], SCALE, bv.w) + madd[(tx << 2) + 3];

            float mx = fmaxf(fmaxf(s[r][0], s[r][1]), fmaxf(s[r][2], s[r][3]));
            #pragma unroll
            for (int off = 8; off >= 1; off >>= 1)
                mx = fmaxf(mx, __shfl_xor_sync(0xffffffffu, mx, off, 16));
            float mnew  = fmaxf(m_i[r], mx);
            float alpha = __expf(m_i[r] - mnew);
            m_i[r] = mnew;

            float rs = 0.f;
            #pragma unroll
            for (int c = 0; c < 4; c++) {
                float p = __expf(s[r][c] - mnew);
                s[r][c] = p;
                rs += p;
            }
            #pragma unroll
            for (int off = 8; off >= 1; off >>= 1)
                rs += __shfl_xor_sync(0xffffffffu, rs, off, 16);
            l_i[r] = l_i[r] * alpha + rs;
            #pragma unroll
            for (int c = 0; c < 4; c++) o[r][c] *= alpha;

            *(float4*)&ps[(ty << 2) + r][tx << 2] =
                make_float4(s[r][0], s[r][1], s[r][2], s[r][3]);
        }
        __syncthreads();

        // O += P V
        #pragma unroll 8
        for (int j = 0; j < 64; j++) {
            float4 vv = *(const float4*)&vs[j][tx << 2];
            float vvv[4] = {vv.x, vv.y, vv.z, vv.w};
            float pp[4];
            #pragma unroll
            for (int r = 0; r < 4; r++) pp[r] = ps[(ty << 2) + r][j];
            #pragma unroll
            for (int r = 0; r < 4; r++)
                #pragma unroll
                for (int c = 0; c < 4; c++)
                    o[r][c] = fmaf(pp[r], vvv[c], o[r][c]);
        }
    }

    // normalize + store
    #pragma unroll
    for (int r = 0; r < 4; r++) {
        float inv = 1.0f / l_i[r];
        float4 ov = make_float4(o[r][0] * inv, o[r][1] * inv,
                                o[r][2] * inv, o[r][3] * inv);
        *(float4*)&g_att[((size_t)(b * N_ + i0 + (ty << 2) + r)) * DM + h * DH + (tx << 2)] = ov;
    }
}

// =====================================================================
extern "C" void kernel_launch(void* const* d_in, const int* in_sizes, int n_in,
                              void* d_out, int out_size)
{
    const float* x        = (const float*)d_in[0];
    const float* coords   = (const float*)d_in[1];
    const unsigned char* mask = (const unsigned char*)d_in[2];
    const float* qkv_w    = (const float*)d_in[3];
    const float* out_w    = (const float*)d_in[4];
    const float* out_b    = (const float*)d_in[5];
    const float* alpha    = (const float*)d_in[6];
    const float* w1       = (const float*)d_in[7];
    const float* b1       = (const float*)d_in[8];
    const float* w2       = (const float*)d_in[9];
    const float* b2       = (const float*)d_in[10];
    const float* cscales  = (const float*)d_in[11];
    float* out            = (float*)d_out;

    // QKV projection: [8192,512] @ [1536,512]^T
    {
        dim3 grid(QKVD / 64, (B_ * N_) / 64);
        k_gemm_qkv<<<grid, 256>>>(x, qkv_w);
    }
    // pairwise bias MLP
    {
        dim3 grid(N_ / 32, N_ / 8, B_);
        dim3 blk(32, 8);
        k_bias<<<grid, blk>>>(coords, cscales, w1, b1, w2, b2, alpha);
    }
    // flash attention with additive bias
    {
        cudaFuncSetAttribute(k_attn, cudaFuncAttributeMaxDynamicSharedMemorySize,
                             ATTN_SMEM);
        dim3 grid(N_ / 64, H_, B_);
        k_attn<<<grid, 256, ATTN_SMEM>>>(mask);
    }
    // output projection: [8192,512] @ [512,512]^T + out_b
    {
        dim3 grid(DM / 64, (B_ * N_) / 64);
        k_gemm_out<<<grid, 256>>>(out_w, out_b, out);
    }
}

// round 5
// speedup vs baseline: 1.2542x; 1.2542x over previous
#include <cuda_runtime.h>
#include <cuda_bf16.h>
#include <cstdint>
#include <math.h>

#define B_   8
#define N_   1024
#define DM   512
#define H_   8
#define DH   64
#define QKVD 1536
#define NS_  1
#define SCALE 0.125f

// ---------------- scratch (device globals; no allocations) ----------------
__device__ float g_qkv[(size_t)B_ * N_ * QKVD];        //  50.3 MB  [b][n][3D]
__device__ float g_bias[(size_t)B_ * H_ * N_ * N_];    // 268.4 MB  [b][h][i][j]
__device__ float g_att[(size_t)B_ * N_ * DM];          //  16.8 MB  [b][n][h*64+d]

// =====================================================================
// mma.sync bf16 GEMM body:  C[M][Nc] = A[M][K] @ W[Nc][K]^T (+ bias)
// Split-bf16 3-pass (hi*hi + lo*hi + hi*lo) for fp32-level accuracy.
// CTA tile 128x128, 8 warps (64x32 each), K-chunk 16, double-buffered.
// NOTE: device-global operands must be bound INSIDE device code (wrappers
// below) — passing __device__ symbols as host-side kernel args is invalid.
// =====================================================================
#define MMA16816(d, a, b) \
  asm volatile("mma.sync.aligned.m16n8k16.row.col.f32.bf16.bf16.f32 " \
    "{%0,%1,%2,%3}, {%4,%5,%6,%7}, {%8,%9}, {%0,%1,%2,%3};" \
    : "+f"((d)[0]), "+f"((d)[1]), "+f"((d)[2]), "+f"((d)[3]) \
    : "r"((a)[0]), "r"((a)[1]), "r"((a)[2]), "r"((a)[3]), \
      "r"((b)[0]), "r"((b)[1]))

#define KC    16
#define LDSB  24                  // bf16 row stride (48 B) -> conflict-free frags
#define PLANE (128 * LDSB)        // bf16 elems per plane
#define STAGE (4 * PLANE)         // Ah | Al | Bh | Bl
#define GEMM_SMEM (2 * STAGE * 2) // bytes (two stages) = 49152

__device__ __forceinline__ void split_store(__nv_bfloat16* hp, __nv_bfloat16* lp,
                                            float4 v)
{
    __nv_bfloat16 h0 = __float2bfloat16(v.x), h1 = __float2bfloat16(v.y);
    __nv_bfloat16 h2 = __float2bfloat16(v.z), h3 = __float2bfloat16(v.w);
    __nv_bfloat16 l0 = __float2bfloat16(v.x - __bfloat162float(h0));
    __nv_bfloat16 l1 = __float2bfloat16(v.y - __bfloat162float(h1));
    __nv_bfloat16 l2 = __float2bfloat16(v.z - __bfloat162float(h2));
    __nv_bfloat16 l3 = __float2bfloat16(v.w - __bfloat162float(h3));
    __nv_bfloat162 a{h0, h1}, b{h2, h3}, c{l0, l1}, d{l2, l3};
    *(uint2*)hp = make_uint2(*(uint32_t*)&a, *(uint32_t*)&b);
    *(uint2*)lp = make_uint2(*(uint32_t*)&c, *(uint32_t*)&d);
}

__device__ __forceinline__ void gemm_mma_body(
    const float* __restrict__ A, const float* __restrict__ W,
    const float* __restrict__ bias, float* __restrict__ C,
    int Nc, int K)
{
    extern __shared__ __nv_bfloat16 smb[];
    const int tid  = threadIdx.x;
    const int wid  = tid >> 5, lane = tid & 31;
    const int g    = lane >> 2, tg = lane & 3;
    const int m0   = blockIdx.y * 128, n0 = blockIdx.x * 128;
    const int wm   = (wid >> 2) * 64,  wn = (wid & 3) * 32;

    float acc[4][4][4];
    #pragma unroll
    for (int mt = 0; mt < 4; mt++)
        #pragma unroll
        for (int nt = 0; nt < 4; nt++)
            #pragma unroll
            for (int r = 0; r < 4; r++) acc[mt][nt][r] = 0.f;

    const int NCH = K / KC;
    const int prow0 = tid >> 2;                 // t=0: rows 0..63
    const int pk4   = (tid & 3) << 2;           // 0,4,8,12
    float4 ra[2], rw[2];

    // ---- prologue: load + store chunk 0
    {
        #pragma unroll
        for (int t = 0; t < 2; t++) {
            int row = prow0 + t * 64;
            ra[t] = *(const float4*)&A[(size_t)(m0 + row) * K + pk4];
            rw[t] = *(const float4*)&W[(size_t)(n0 + row) * K + pk4];
        }
        __nv_bfloat16* s = smb;
        #pragma unroll
        for (int t = 0; t < 2; t++) {
            int row = prow0 + t * 64;
            int off = row * LDSB + pk4;
            split_store(s + off,             s + PLANE + off,     ra[t]);
            split_store(s + 2 * PLANE + off, s + 3 * PLANE + off, rw[t]);
        }
    }

    for (int c = 0; c < NCH; c++) {
        __syncthreads();          // stage c&1 ready for all warps

        // prefetch next chunk into registers
        if (c + 1 < NCH) {
            const int k0 = (c + 1) * KC;
            #pragma unroll
            for (int t = 0; t < 2; t++) {
                int row = prow0 + t * 64;
                ra[t] = *(const float4*)&A[(size_t)(m0 + row) * K + k0 + pk4];
                rw[t] = *(const float4*)&W[(size_t)(n0 + row) * K + k0 + pk4];
            }
        }

        // ---- compute on stage c&1
        {
            const __nv_bfloat16* Ah = smb + (c & 1) * STAGE;
            const __nv_bfloat16* Al = Ah + PLANE;
            const __nv_bfloat16* Bh = Ah + 2 * PLANE;
            const __nv_bfloat16* Bl = Ah + 3 * PLANE;

            uint32_t ah[4][4], al[4][4], bh[4][2], bl[4][2];
            #pragma unroll
            for (int mt = 0; mt < 4; mt++) {
                int base = (wm + mt * 16 + g) * LDSB + tg * 2;
                ah[mt][0] = *(const uint32_t*)(Ah + base);
                ah[mt][1] = *(const uint32_t*)(Ah + base + 8 * LDSB);
                ah[mt][2] = *(const uint32_t*)(Ah + base + 8);
                ah[mt][3] = *(const uint32_t*)(Ah + base + 8 * LDSB + 8);
                al[mt][0] = *(const uint32_t*)(Al + base);
                al[mt][1] = *(const uint32_t*)(Al + base + 8 * LDSB);
                al[mt][2] = *(const uint32_t*)(Al + base + 8);
                al[mt][3] = *(const uint32_t*)(Al + base + 8 * LDSB + 8);
            }
            #pragma unroll
            for (int nt = 0; nt < 4; nt++) {
                int base = (wn + nt * 8 + g) * LDSB + tg * 2;
                bh[nt][0] = *(const uint32_t*)(Bh + base);
                bh[nt][1] = *(const uint32_t*)(Bh + base + 8);
                bl[nt][0] = *(const uint32_t*)(Bl + base);
                bl[nt][1] = *(const uint32_t*)(Bl + base + 8);
            }
            #pragma unroll
            for (int mt = 0; mt < 4; mt++)
                #pragma unroll
                for (int nt = 0; nt < 4; nt++)
                    MMA16816(acc[mt][nt], ah[mt], bh[nt]);
            #pragma unroll
            for (int mt = 0; mt < 4; mt++)
                #pragma unroll
                for (int nt = 0; nt < 4; nt++)
                    MMA16816(acc[mt][nt], al[mt], bh[nt]);
            #pragma unroll
            for (int mt = 0; mt < 4; mt++)
                #pragma unroll
                for (int nt = 0; nt < 4; nt++)
                    MMA16816(acc[mt][nt], ah[mt], bl[nt]);
        }

        // store prefetched chunk into the other stage
        if (c + 1 < NCH) {
            __nv_bfloat16* s = smb + ((c + 1) & 1) * STAGE;
            #pragma unroll
            for (int t = 0; t < 2; t++) {
                int row = prow0 + t * 64;
                int off = row * LDSB + pk4;
                split_store(s + off,             s + PLANE + off,     ra[t]);
                split_store(s + 2 * PLANE + off, s + 3 * PLANE + off, rw[t]);
            }
        }
    }

    // ---- epilogue
    #pragma unroll
    for (int mt = 0; mt < 4; mt++) {
        #pragma unroll
        for (int nt = 0; nt < 4; nt++) {
            int row = m0 + wm + mt * 16 + g;
            int col = n0 + wn + nt * 8 + tg * 2;
            float bx = 0.f, by = 0.f;
            if (bias) { bx = bias[col]; by = bias[col + 1]; }
            *(float2*)&C[(size_t)row * Nc + col] =
                make_float2(acc[mt][nt][0] + bx, acc[mt][nt][1] + by);
            *(float2*)&C[(size_t)(row + 8) * Nc + col] =
                make_float2(acc[mt][nt][2] + bx, acc[mt][nt][3] + by);
        }
    }
}

// wrappers: bind device globals IN DEVICE CODE (the R3 bug was passing
// g_qkv / g_att as host-side kernel arguments — host shadow address).
__global__ void __launch_bounds__(256)
k_gemm_qkv_mma(const float* __restrict__ x, const float* __restrict__ qkv_w)
{
    gemm_mma_body(x, qkv_w, nullptr, g_qkv, QKVD, DM);
}

__global__ void __launch_bounds__(256)
k_gemm_out_mma(const float* __restrict__ out_w, const float* __restrict__ out_b,
               float* __restrict__ out)
{
    gemm_mma_body(g_att, out_w, out_b, out, DM, DM);
}

// =====================================================================
// Pairwise bias MLP (unchanged, R1-proven)
// =====================================================================
__global__ void __launch_bounds__(256)
k_bias(const float* __restrict__ coords, const float* __restrict__ cs,
       const float* __restrict__ w1, const float* __restrict__ b1,
       const float* __restrict__ w2, const float* __restrict__ b2,
       const float* __restrict__ alpha_p)
{
    __shared__ float sw1[32][4];
    __shared__ float sb1[32];
    __shared__ float sw2[8][32];
    __shared__ float sb2[8];
    __shared__ float ssc[3];
    __shared__ float salpha;

    const int tid = threadIdx.y * 32 + threadIdx.x;
    if (tid < 128) ((float*)sw1)[tid] = w1[tid];
    if (tid < 256) ((float*)sw2)[tid] = w2[tid];
    if (tid < 32)  sb1[tid] = b1[tid];
    if (tid < 8)   sb2[tid] = b2[tid];
    if (tid < 3)   ssc[tid] = cs[tid];
    if (tid == 0)  salpha = alpha_p[0];
    __syncthreads();

    const int b = blockIdx.z;
    const int i = blockIdx.y * 8 + threadIdx.y;
    const int j = blockIdx.x * 32 + threadIdx.x;

    float out[8];
    #pragma unroll
    for (int h = 0; h < 8; h++) out[h] = 0.f;

    if (i >= NS_ && j >= NS_) {
        const float* ci = &coords[((size_t)b * N_ + i) * 3];
        const float* cj = &coords[((size_t)b * N_ + j) * 3];
        float dx = (ci[0] - cj[0]) / ssc[0];
        float dy = (ci[1] - cj[1]) / ssc[1];
        float dz = (ci[2] - cj[2]) / ssc[2];
        float dist = sqrtf(dx * dx + dy * dy + dz * dz);

        #pragma unroll
        for (int h = 0; h < 8; h++) out[h] = sb2[h];

        #pragma unroll 8
        for (int k = 0; k < 32; k++) {
            float t = fmaf(sw1[k][0], dx,
                      fmaf(sw1[k][1], dy,
                      fmaf(sw1[k][2], dz,
                      fmaf(sw1[k][3], dist, sb1[k]))));
            float g = 0.5f * t * (1.0f + erff(t * 0.70710678118654752f));
            #pragma unroll
            for (int h = 0; h < 8; h++)
                out[h] = fmaf(sw2[h][k], g, out[h]);
        }
    }

    const size_t base = ((size_t)b * H_ * N_ + i) * N_ + j;
    #pragma unroll
    for (int h = 0; h < 8; h++)
        g_bias[base + (size_t)h * N_ * N_] = salpha * out[h];
}

// =====================================================================
// Flash attention (unchanged, R1-proven)
// =====================================================================
#define ATTN_SMEM ((4 * 64 * 68 + 64) * 4)

__global__ void __launch_bounds__(256)
k_attn(const unsigned char* __restrict__ mask)
{
    extern __shared__ float sm[];
    float (*qs)[68] = (float(*)[68])(sm);
    float (*ks)[68] = (float(*)[68])(sm + 64 * 68);
    float (*vs)[68] = (float(*)[68])(sm + 2 * 64 * 68);
    float (*ps)[68] = (float(*)[68])(sm + 3 * 64 * 68);
    float* madd     = sm + 4 * 64 * 68;

    const int b = blockIdx.z, h = blockIdx.y;
    const int i0 = blockIdx.x * 64;
    const int tid = threadIdx.x;
    const int tx = tid & 15, ty = tid >> 4;

    #pragma unroll
    for (int t = 0; t < 4; t++) {
        int lin = tid + t * 256;
        int row = lin >> 4;
        int d4  = (lin & 15) << 2;
        float4 v = *(const float4*)&g_qkv[((size_t)(b * N_ + i0 + row)) * QKVD + h * DH + d4];
        qs[d4 + 0][row] = v.x; qs[d4 + 1][row] = v.y;
        qs[d4 + 2][row] = v.z; qs[d4 + 3][row] = v.w;
    }

    float m_i[4], l_i[4], o[4][4];
    #pragma unroll
    for (int r = 0; r < 4; r++) {
        m_i[r] = -INFINITY; l_i[r] = 0.f;
        #pragma unroll
        for (int c = 0; c < 4; c++) o[r][c] = 0.f;
    }

    const size_t brow = (size_t)(b * H_ + h) * N_;

    for (int j0 = 0; j0 < N_; j0 += 64) {
        __syncthreads();

        #pragma unroll
        for (int t = 0; t < 4; t++) {
            int lin = tid + t * 256;
            int row = lin >> 4;
            int d4  = (lin & 15) << 2;
            size_t rb = ((size_t)(b * N_ + j0 + row)) * QKVD + h * DH + d4;
            float4 kv = *(const float4*)&g_qkv[rb + DM];
            ks[d4 + 0][row] = kv.x; ks[d4 + 1][row] = kv.y;
            ks[d4 + 2][row] = kv.z; ks[d4 + 3][row] = kv.w;
            float4 vv = *(const float4*)&g_qkv[rb + 2 * DM];
            *(float4*)&vs[row][d4] = vv;
        }
        if (tid < 64)
            madd[tid] = mask[(size_t)b * N_ + j0 + tid] ? -1e30f : 0.0f;
        __syncthreads();

        float s[4][4] = {};
        #pragma unroll 16
        for (int kk = 0; kk < 64; kk++) {
            float4 a  = *(const float4*)&qs[kk][ty << 2];
            float4 bb = *(const float4*)&ks[kk][tx << 2];
            float av[4] = {a.x, a.y, a.z, a.w};
            float bv[4] = {bb.x, bb.y, bb.z, bb.w};
            #pragma unroll
            for (int r = 0; r < 4; r++)
                #pragma unroll
                for (int c = 0; c < 4; c++)
                    s[r][c] = fmaf(av[r], bv[c], s[r][c]);
        }

        #pragma unroll
        for (int r = 0; r < 4; r++) {
            float4 bv = *(const float4*)&g_bias[(brow + i0 + (ty << 2) + r) * N_ + j0 + (tx << 2)];
            s[r][0] = fmaf(s[r][0], SCALE, bv.x) + madd[(tx << 2) + 0];
            s[r][1] = fmaf(s[r][1], SCALE, bv.y) + madd[(tx << 2) + 1];
            s[r][2] = fmaf(s[r][2], SCALE, bv.z) + madd[(tx << 2) + 2];
            s[r][3] = fmaf(s[r][3], SCALE, bv.w) + madd[(tx << 2) + 3];

            float mx = fmaxf(fmaxf(s[r][0], s[r][1]), fmaxf(s[r][2], s[r][3]));
            #pragma unroll
            for (int off = 8; off >= 1; off >>= 1)
                mx = fmaxf(mx, __shfl_xor_sync(0xffffffffu, mx, off, 16));
            float mnew  = fmaxf(m_i[r], mx);
            float alpha = __expf(m_i[r] - mnew);
            m_i[r] = mnew;

            float rs = 0.f;
            #pragma unroll
            for (int c = 0; c < 4; c++) {
                float p = __expf(s[r][c] - mnew);
                s[r][c] = p;
                rs += p;
            }
            #pragma unroll
            for (int off = 8; off >= 1; off >>= 1)
                rs += __shfl_xor_sync(0xffffffffu, rs, off, 16);
            l_i[r] = l_i[r] * alpha + rs;
            #pragma unroll
            for (int c = 0; c < 4; c++) o[r][c] *= alpha;

            *(float4*)&ps[(ty << 2) + r][tx << 2] =
                make_float4(s[r][0], s[r][1], s[r][2], s[r][3]);
        }
        __syncthreads();

        #pragma unroll 8
        for (int j = 0; j < 64; j++) {
            float4 vv = *(const float4*)&vs[j][tx << 2];
            float vvv[4] = {vv.x, vv.y, vv.z, vv.w};
            float pp[4];
            #pragma unroll
            for (int r = 0; r < 4; r++) pp[r] = ps[(ty << 2) + r][j];
            #pragma unroll
            for (int r = 0; r < 4; r++)
                #pragma unroll
                for (int c = 0; c < 4; c++)
                    o[r][c] = fmaf(pp[r], vvv[c], o[r][c]);
        }
    }

    #pragma unroll
    for (int r = 0; r < 4; r++) {
        float inv = 1.0f / l_i[r];
        float4 ov = make_float4(o[r][0] * inv, o[r][1] * inv,
                                o[r][2] * inv, o[r][3] * inv);
        *(float4*)&g_att[((size_t)(b * N_ + i0 + (ty << 2) + r)) * DM + h * DH + (tx << 2)] = ov;
    }
}

// =====================================================================
extern "C" void kernel_launch(void* const* d_in, const int* in_sizes, int n_in,
                              void* d_out, int out_size)
{
    const float* x        = (const float*)d_in[0];
    const float* coords   = (const float*)d_in[1];
    const unsigned char* mask = (const unsigned char*)d_in[2];
    const float* qkv_w    = (const float*)d_in[3];
    const float* out_w    = (const float*)d_in[4];
    const float* out_b    = (const float*)d_in[5];
    const float* alpha    = (const float*)d_in[6];
    const float* w1       = (const float*)d_in[7];
    const float* b1       = (const float*)d_in[8];
    const float* w2       = (const float*)d_in[9];
    const float* b2       = (const float*)d_in[10];
    const float* cscales  = (const float*)d_in[11];
    float* out            = (float*)d_out;

    cudaFuncSetAttribute(k_gemm_qkv_mma, cudaFuncAttributeMaxDynamicSharedMemorySize,
                         GEMM_SMEM);
    cudaFuncSetAttribute(k_gemm_out_mma, cudaFuncAttributeMaxDynamicSharedMemorySize,
                         GEMM_SMEM);
    cudaFuncSetAttribute(k_attn, cudaFuncAttributeMaxDynamicSharedMemorySize,
                         ATTN_SMEM);

    // QKV projection (mma.sync split-bf16): [8192,512] @ [1536,512]^T
    {
        dim3 grid(QKVD / 128, (B_ * N_) / 128);
        k_gemm_qkv_mma<<<grid, 256, GEMM_SMEM>>>(x, qkv_w);
    }
    // pairwise bias MLP
    {
        dim3 grid(N_ / 32, N_ / 8, B_);
        dim3 blk(32, 8);
        k_bias<<<grid, blk>>>(coords, cscales, w1, b1, w2, b2, alpha);
    }
    // flash attention with additive bias
    {
        dim3 grid(N_ / 64, H_, B_);
        k_attn<<<grid, 256, ATTN_SMEM>>>(mask);
    }
    // output projection (mma.sync split-bf16): [8192,512] @ [512,512]^T + out_b
    {
        dim3 grid(DM / 128, (B_ * N_) / 128);
        k_gemm_out_mma<<<grid, 256, GEMM_SMEM>>>(out_w, out_b, out);
    }
}

// round 6
// speedup vs baseline: 1.6200x; 1.2917x over previous
#include <cuda_runtime.h>
#include <cuda_bf16.h>
#include <cstdint>
#include <math.h>

#define B_   8
#define N_   1024
#define DM   512
#define H_   8
#define DH   64
#define QKVD 1536
#define NS_  1
#define SCALE 0.125f

// ---------------- scratch (device globals; no allocations) ----------------
__device__ float g_qkv[(size_t)B_ * N_ * QKVD];        //  50.3 MB  [b][n][3D]
__device__ float g_bias[(size_t)B_ * H_ * N_ * N_];    // 268.4 MB  [b][h][i][j]
__device__ float g_att[(size_t)B_ * N_ * DM];          //  16.8 MB  [b][n][h*64+d]

// =====================================================================
// common helpers
// =====================================================================
#define MMA16816(d, a, b) \
  asm volatile("mma.sync.aligned.m16n8k16.row.col.f32.bf16.bf16.f32 " \
    "{%0,%1,%2,%3}, {%4,%5,%6,%7}, {%8,%9}, {%0,%1,%2,%3};" \
    : "+f"((d)[0]), "+f"((d)[1]), "+f"((d)[2]), "+f"((d)[3]) \
    : "r"((a)[0]), "r"((a)[1]), "r"((a)[2]), "r"((a)[3]), \
      "r"((b)[0]), "r"((b)[1]))

#define LDMX2T(r0, r1, addr) \
  asm volatile("ldmatrix.sync.aligned.m8n8.x2.trans.shared.b16 {%0,%1}, [%2];" \
    : "=r"(r0), "=r"(r1) : "r"(addr))

__device__ __forceinline__ void split2(float a, float b, uint32_t& hi, uint32_t& lo)
{
    __nv_bfloat16 ha = __float2bfloat16(a), hb = __float2bfloat16(b);
    __nv_bfloat16 la = __float2bfloat16(a - __bfloat162float(ha));
    __nv_bfloat16 lb = __float2bfloat16(b - __bfloat162float(hb));
    __nv_bfloat162 h{ha, hb}, l{la, lb};
    hi = *(uint32_t*)&h; lo = *(uint32_t*)&l;
}

__device__ __forceinline__ void split_store(__nv_bfloat16* hp, __nv_bfloat16* lp,
                                            float4 v)
{
    uint32_t h0, l0, h1, l1;
    split2(v.x, v.y, h0, l0);
    split2(v.z, v.w, h1, l1);
    *(uint2*)hp = make_uint2(h0, h1);
    *(uint2*)lp = make_uint2(l0, l1);
}

// fast exp on the FMA pipe (MUFU-free). x <= ~0 expected; rel err ~2e-8.
__device__ __forceinline__ float exp_fast(float x)
{
    x = fmaxf(x, -87.0f);
    const float L2E   = 1.4426950408889634f;
    const float MAGIC = 12582912.0f;            // 1.5 * 2^23
    float t = fmaf(x, L2E, MAGIC);
    int   i = __float_as_int(t);
    float n = t - MAGIC;
    float f = fmaf(x, L2E, -n);                 // in [-0.5, 0.5]
    float p = 1.5403530393e-4f;
    p = fmaf(p, f, 1.3333558146e-3f);
    p = fmaf(p, f, 9.6181291076e-3f);
    p = fmaf(p, f, 5.5504108665e-2f);
    p = fmaf(p, f, 2.4022650696e-1f);
    p = fmaf(p, f, 6.9314718056e-1f);
    p = fmaf(p, f, 1.0f);
    return __int_as_float(__float_as_int(p) + (i << 23));
}

// =====================================================================
// mma.sync bf16 GEMM body (unchanged, R5-proven)
// =====================================================================
#define KC    16
#define LDSB  24
#define PLANE (128 * LDSB)
#define STAGE (4 * PLANE)
#define GEMM_SMEM (2 * STAGE * 2)

__device__ __forceinline__ void gemm_mma_body(
    const float* __restrict__ A, const float* __restrict__ W,
    const float* __restrict__ bias, float* __restrict__ C,
    int Nc, int K)
{
    extern __shared__ __nv_bfloat16 smb[];
    const int tid  = threadIdx.x;
    const int wid  = tid >> 5, lane = tid & 31;
    const int g    = lane >> 2, tg = lane & 3;
    const int m0   = blockIdx.y * 128, n0 = blockIdx.x * 128;
    const int wm   = (wid >> 2) * 64,  wn = (wid & 3) * 32;

    float acc[4][4][4];
    #pragma unroll
    for (int mt = 0; mt < 4; mt++)
        #pragma unroll
        for (int nt = 0; nt < 4; nt++)
            #pragma unroll
            for (int r = 0; r < 4; r++) acc[mt][nt][r] = 0.f;

    const int NCH = K / KC;
    const int prow0 = tid >> 2;
    const int pk4   = (tid & 3) << 2;
    float4 ra[2], rw[2];

    {
        #pragma unroll
        for (int t = 0; t < 2; t++) {
            int row = prow0 + t * 64;
            ra[t] = *(const float4*)&A[(size_t)(m0 + row) * K + pk4];
            rw[t] = *(const float4*)&W[(size_t)(n0 + row) * K + pk4];
        }
        __nv_bfloat16* s = smb;
        #pragma unroll
        for (int t = 0; t < 2; t++) {
            int row = prow0 + t * 64;
            int off = row * LDSB + pk4;
            split_store(s + off,             s + PLANE + off,     ra[t]);
            split_store(s + 2 * PLANE + off, s + 3 * PLANE + off, rw[t]);
        }
    }

    for (int c = 0; c < NCH; c++) {
        __syncthreads();

        if (c + 1 < NCH) {
            const int k0 = (c + 1) * KC;
            #pragma unroll
            for (int t = 0; t < 2; t++) {
                int row = prow0 + t * 64;
                ra[t] = *(const float4*)&A[(size_t)(m0 + row) * K + k0 + pk4];
                rw[t] = *(const float4*)&W[(size_t)(n0 + row) * K + k0 + pk4];
            }
        }

        {
            const __nv_bfloat16* Ah = smb + (c & 1) * STAGE;
            const __nv_bfloat16* Al = Ah + PLANE;
            const __nv_bfloat16* Bh = Ah + 2 * PLANE;
            const __nv_bfloat16* Bl = Ah + 3 * PLANE;

            uint32_t ah[4][4], al[4][4], bh[4][2], bl[4][2];
            #pragma unroll
            for (int mt = 0; mt < 4; mt++) {
                int base = (wm + mt * 16 + g) * LDSB + tg * 2;
                ah[mt][0] = *(const uint32_t*)(Ah + base);
                ah[mt][1] = *(const uint32_t*)(Ah + base + 8 * LDSB);
                ah[mt][2] = *(const uint32_t*)(Ah + base + 8);
                ah[mt][3] = *(const uint32_t*)(Ah + base + 8 * LDSB + 8);
                al[mt][0] = *(const uint32_t*)(Al + base);
                al[mt][1] = *(const uint32_t*)(Al + base + 8 * LDSB);
                al[mt][2] = *(const uint32_t*)(Al + base + 8);
                al[mt][3] = *(const uint32_t*)(Al + base + 8 * LDSB + 8);
            }
            #pragma unroll
            for (int nt = 0; nt < 4; nt++) {
                int base = (wn + nt * 8 + g) * LDSB + tg * 2;
                bh[nt][0] = *(const uint32_t*)(Bh + base);
                bh[nt][1] = *(const uint32_t*)(Bh + base + 8);
                bl[nt][0] = *(const uint32_t*)(Bl + base);
                bl[nt][1] = *(const uint32_t*)(Bl + base + 8);
            }
            #pragma unroll
            for (int mt = 0; mt < 4; mt++)
                #pragma unroll
                for (int nt = 0; nt < 4; nt++)
                    MMA16816(acc[mt][nt], ah[mt], bh[nt]);
            #pragma unroll
            for (int mt = 0; mt < 4; mt++)
                #pragma unroll
                for (int nt = 0; nt < 4; nt++)
                    MMA16816(acc[mt][nt], al[mt], bh[nt]);
            #pragma unroll
            for (int mt = 0; mt < 4; mt++)
                #pragma unroll
                for (int nt = 0; nt < 4; nt++)
                    MMA16816(acc[mt][nt], ah[mt], bl[nt]);
        }

        if (c + 1 < NCH) {
            __nv_bfloat16* s = smb + ((c + 1) & 1) * STAGE;
            #pragma unroll
            for (int t = 0; t < 2; t++) {
                int row = prow0 + t * 64;
                int off = row * LDSB + pk4;
                split_store(s + off,             s + PLANE + off,     ra[t]);
                split_store(s + 2 * PLANE + off, s + 3 * PLANE + off, rw[t]);
            }
        }
    }

    #pragma unroll
    for (int mt = 0; mt < 4; mt++) {
        #pragma unroll
        for (int nt = 0; nt < 4; nt++) {
            int row = m0 + wm + mt * 16 + g;
            int col = n0 + wn + nt * 8 + tg * 2;
            float bx = 0.f, by = 0.f;
            if (bias) { bx = bias[col]; by = bias[col + 1]; }
            *(float2*)&C[(size_t)row * Nc + col] =
                make_float2(acc[mt][nt][0] + bx, acc[mt][nt][1] + by);
            *(float2*)&C[(size_t)(row + 8) * Nc + col] =
                make_float2(acc[mt][nt][2] + bx, acc[mt][nt][3] + by);
        }
    }
}

__global__ void __launch_bounds__(256)
k_gemm_qkv_mma(const float* __restrict__ x, const float* __restrict__ qkv_w)
{
    gemm_mma_body(x, qkv_w, nullptr, g_qkv, QKVD, DM);
}

__global__ void __launch_bounds__(256)
k_gemm_out_mma(const float* __restrict__ out_w, const float* __restrict__ out_b,
               float* __restrict__ out)
{
    gemm_mma_body(g_att, out_w, out_b, out, DM, DM);
}

// =====================================================================
// Pairwise bias MLP (unchanged, R1-proven)
// =====================================================================
__global__ void __launch_bounds__(256)
k_bias(const float* __restrict__ coords, const float* __restrict__ cs,
       const float* __restrict__ w1, const float* __restrict__ b1,
       const float* __restrict__ w2, const float* __restrict__ b2,
       const float* __restrict__ alpha_p)
{
    __shared__ float sw1[32][4];
    __shared__ float sb1[32];
    __shared__ float sw2[8][32];
    __shared__ float sb2[8];
    __shared__ float ssc[3];
    __shared__ float salpha;

    const int tid = threadIdx.y * 32 + threadIdx.x;
    if (tid < 128) ((float*)sw1)[tid] = w1[tid];
    if (tid < 256) ((float*)sw2)[tid] = w2[tid];
    if (tid < 32)  sb1[tid] = b1[tid];
    if (tid < 8)   sb2[tid] = b2[tid];
    if (tid < 3)   ssc[tid] = cs[tid];
    if (tid == 0)  salpha = alpha_p[0];
    __syncthreads();

    const int b = blockIdx.z;
    const int i = blockIdx.y * 8 + threadIdx.y;
    const int j = blockIdx.x * 32 + threadIdx.x;

    float out[8];
    #pragma unroll
    for (int h = 0; h < 8; h++) out[h] = 0.f;

    if (i >= NS_ && j >= NS_) {
        const float* ci = &coords[((size_t)b * N_ + i) * 3];
        const float* cj = &coords[((size_t)b * N_ + j) * 3];
        float dx = (ci[0] - cj[0]) / ssc[0];
        float dy = (ci[1] - cj[1]) / ssc[1];
        float dz = (ci[2] - cj[2]) / ssc[2];
        float dist = sqrtf(dx * dx + dy * dy + dz * dz);

        #pragma unroll
        for (int h = 0; h < 8; h++) out[h] = sb2[h];

        #pragma unroll 8
        for (int k = 0; k < 32; k++) {
            float t = fmaf(sw1[k][0], dx,
                      fmaf(sw1[k][1], dy,
                      fmaf(sw1[k][2], dz,
                      fmaf(sw1[k][3], dist, sb1[k]))));
            float g = 0.5f * t * (1.0f + erff(t * 0.70710678118654752f));
            #pragma unroll
            for (int h = 0; h < 8; h++)
                out[h] = fmaf(sw2[h][k], g, out[h]);
        }
    }

    const size_t base = ((size_t)b * H_ * N_ + i) * N_ + j;
    #pragma unroll
    for (int h = 0; h < 8; h++)
        g_bias[base + (size_t)h * N_ * N_] = salpha * out[h];
}

// =====================================================================
// Tensor-core flash attention.
// CTA: 128 q-rows x one (b,h). 8 warps, each warp owns 16 rows (full width).
// S = QK^T and O += P V via m16n8k16 with 3-pass bf16 split.
// Softmax state fp32 in registers; exp on FMA pipe (exp_fast).
// =====================================================================
#define LQ 72   // bf16 row stride: banks (4g+tg) mod 32 all distinct
// smem layout (bf16 units):
//  Qh @ 0         (128*LQ)   Ql @ 9216
//  Kh @ 18432     (64*LQ)    Kl @ 23040
//  Vh @ 27648     (64*LQ)    Vl @ 32256
//  total 36864 bf16 = 73728 B ; madd (64 f32) @ 73728
#define ATTN_SMEM2 (36864 * 2 + 64 * 4)

__global__ void __launch_bounds__(256)
k_attn_mma(const unsigned char* __restrict__ mask)
{
    extern __shared__ __nv_bfloat16 sma[];
    __nv_bfloat16* Qh = sma;
    __nv_bfloat16* Ql = sma + 9216;
    __nv_bfloat16* Kh = sma + 18432;
    __nv_bfloat16* Kl = sma + 23040;
    __nv_bfloat16* Vh = sma + 27648;
    __nv_bfloat16* Vl = sma + 32256;
    float* madd = (float*)(sma + 36864);

    const int b = blockIdx.z, h = blockIdx.y;
    const int i0 = blockIdx.x * 128;
    const int tid = threadIdx.x;
    const int w = tid >> 5, lane = tid & 31;
    const int g = lane >> 2, tg = lane & 3;

    const uint32_t vh_u32 = (uint32_t)__cvta_generic_to_shared(Vh);
    const uint32_t vl_u32 = (uint32_t)__cvta_generic_to_shared(Vl);

    // ---- load Q tile (128 x 64), split hi/lo
    #pragma unroll
    for (int t = 0; t < 8; t++) {
        int f = tid + t * 256;          // 0..2047 (128 rows x 16 float4)
        int row = f >> 4;
        int c4 = (f & 15) << 2;
        float4 v = *(const float4*)&g_qkv[((size_t)(b * N_ + i0 + row)) * QKVD + h * DH + c4];
        split_store(Qh + row * LQ + c4, Ql + row * LQ + c4, v);
    }

    float oacc[8][4];
    #pragma unroll
    for (int nt = 0; nt < 8; nt++)
        #pragma unroll
        for (int r = 0; r < 4; r++) oacc[nt][r] = 0.f;
    float m0r = -INFINITY, m1r = -INFINITY, l0r = 0.f, l1r = 0.f;

    const size_t bias_row0 = ((size_t)(b * H_ + h) * N_ + (i0 + w * 16 + g)) * N_;
    const int qrow = (w * 16 + g) * LQ + tg * 2;

    for (int j0 = 0; j0 < N_; j0 += 64) {
        __syncthreads();     // previous iter's K/V reads done

        // ---- load K,V chunk (64x64 each), split hi/lo; V natural [j][d]
        #pragma unroll
        for (int t = 0; t < 4; t++) {
            int f = tid + t * 256;      // 64 rows x 16 float4
            int row = f >> 4;
            int c4 = (f & 15) << 2;
            size_t rb = ((size_t)(b * N_ + j0 + row)) * QKVD + h * DH + c4;
            float4 kv = *(const float4*)&g_qkv[rb + DM];
            split_store(Kh + row * LQ + c4, Kl + row * LQ + c4, kv);
            float4 vv = *(const float4*)&g_qkv[rb + 2 * DM];
            split_store(Vh + row * LQ + c4, Vl + row * LQ + c4, vv);
        }
        if (tid < 64)
            madd[tid] = mask[(size_t)b * N_ + j0 + tid] ? -1e30f : 0.0f;
        __syncthreads();

        // ---- S = Q K^T  (16 x 64 per warp), 3-pass split
        float sacc[8][4];
        #pragma unroll
        for (int nt = 0; nt < 8; nt++)
            #pragma unroll
            for (int r = 0; r < 4; r++) sacc[nt][r] = 0.f;

        #pragma unroll
        for (int kc = 0; kc < 4; kc++) {
            int qb = qrow + kc * 16;
            uint32_t qh[4], ql[4];
            qh[0] = *(const uint32_t*)(Qh + qb);
            qh[1] = *(const uint32_t*)(Qh + qb + 8 * LQ);
            qh[2] = *(const uint32_t*)(Qh + qb + 8);
            qh[3] = *(const uint32_t*)(Qh + qb + 8 * LQ + 8);
            ql[0] = *(const uint32_t*)(Ql + qb);
            ql[1] = *(const uint32_t*)(Ql + qb + 8 * LQ);
            ql[2] = *(const uint32_t*)(Ql + qb + 8);
            ql[3] = *(const uint32_t*)(Ql + qb + 8 * LQ + 8);
            #pragma unroll
            for (int nt = 0; nt < 8; nt++) {
                int kb = (8 * nt + g) * LQ + kc * 16 + tg * 2;
                uint32_t bh[2], bl[2];
                bh[0] = *(const uint32_t*)(Kh + kb);
                bh[1] = *(const uint32_t*)(Kh + kb + 8);
                bl[0] = *(const uint32_t*)(Kl + kb);
                bl[1] = *(const uint32_t*)(Kl + kb + 8);
                MMA16816(sacc[nt], qh, bh);
                MMA16816(sacc[nt], ql, bh);
                MMA16816(sacc[nt], qh, bl);
            }
        }

        // ---- logits = S*scale + bias + mask
        const float* bp0 = &g_bias[bias_row0 + j0];
        const float* bp1 = bp0 + 8 * N_;
        #pragma unroll
        for (int nt = 0; nt < 8; nt++) {
            int col = 8 * nt + tg * 2;
            float2 mz = *(float2*)&madd[col];
            float2 bz0 = *(const float2*)&bp0[col];
            float2 bz1 = *(const float2*)&bp1[col];
            sacc[nt][0] = fmaf(sacc[nt][0], SCALE, bz0.x) + mz.x;
            sacc[nt][1] = fmaf(sacc[nt][1], SCALE, bz0.y) + mz.y;
            sacc[nt][2] = fmaf(sacc[nt][2], SCALE, bz1.x) + mz.x;
            sacc[nt][3] = fmaf(sacc[nt][3], SCALE, bz1.y) + mz.y;
        }

        // ---- online softmax (rows g and g+8; quad-local reductions)
        float mx0 = -INFINITY, mx1 = -INFINITY;
        #pragma unroll
        for (int nt = 0; nt < 8; nt++) {
            mx0 = fmaxf(mx0, fmaxf(sacc[nt][0], sacc[nt][1]));
            mx1 = fmaxf(mx1, fmaxf(sacc[nt][2], sacc[nt][3]));
        }
        mx0 = fmaxf(mx0, __shfl_xor_sync(0xffffffffu, mx0, 1));
        mx0 = fmaxf(mx0, __shfl_xor_sync(0xffffffffu, mx0, 2));
        mx1 = fmaxf(mx1, __shfl_xor_sync(0xffffffffu, mx1, 1));
        mx1 = fmaxf(mx1, __shfl_xor_sync(0xffffffffu, mx1, 2));

        float mn0 = fmaxf(m0r, mx0), mn1 = fmaxf(m1r, mx1);
        float a0 = exp_fast(m0r - mn0), a1 = exp_fast(m1r - mn1);
        m0r = mn0; m1r = mn1;

        float rs0 = 0.f, rs1 = 0.f;
        #pragma unroll
        for (int nt = 0; nt < 8; nt++) {
            float p0 = exp_fast(sacc[nt][0] - mn0);
            float p1 = exp_fast(sacc[nt][1] - mn0);
            float p2 = exp_fast(sacc[nt][2] - mn1);
            float p3 = exp_fast(sacc[nt][3] - mn1);
            sacc[nt][0] = p0; sacc[nt][1] = p1;
            sacc[nt][2] = p2; sacc[nt][3] = p3;
            rs0 += p0 + p1; rs1 += p2 + p3;
        }
        rs0 += __shfl_xor_sync(0xffffffffu, rs0, 1);
        rs0 += __shfl_xor_sync(0xffffffffu, rs0, 2);
        rs1 += __shfl_xor_sync(0xffffffffu, rs1, 1);
        rs1 += __shfl_xor_sync(0xffffffffu, rs1, 2);
        l0r = l0r * a0 + rs0;
        l1r = l1r * a1 + rs1;
        #pragma unroll
        for (int nt = 0; nt < 8; nt++) {
            oacc[nt][0] *= a0; oacc[nt][1] *= a0;
            oacc[nt][2] *= a1; oacc[nt][3] *= a1;
        }

        // ---- O += P V  (P in-register repack; V via ldmatrix.trans)
        #pragma unroll
        for (int kc = 0; kc < 4; kc++) {
            uint32_t ph[4], pl[4];
            split2(sacc[2 * kc][0],     sacc[2 * kc][1],     ph[0], pl[0]);
            split2(sacc[2 * kc][2],     sacc[2 * kc][3],     ph[1], pl[1]);
            split2(sacc[2 * kc + 1][0], sacc[2 * kc + 1][1], ph[2], pl[2]);
            split2(sacc[2 * kc + 1][2], sacc[2 * kc + 1][3], ph[3], pl[3]);

            uint32_t rowoff = (uint32_t)((16 * kc + (lane & 15)) * LQ) * 2;
            #pragma unroll
            for (int ntd = 0; ntd < 8; ntd++) {
                uint32_t bh[2], bl[2];
                LDMX2T(bh[0], bh[1], vh_u32 + rowoff + ntd * 16);
                LDMX2T(bl[0], bl[1], vl_u32 + rowoff + ntd * 16);
                MMA16816(oacc[ntd], ph, bh);
                MMA16816(oacc[ntd], pl, bh);
                MMA16816(oacc[ntd], ph, bl);
            }
        }
    }

    // ---- normalize + store
    float inv0 = 1.0f / l0r, inv1 = 1.0f / l1r;
    const size_t orow0 = ((size_t)(b * N_ + i0 + w * 16 + g)) * DM + h * DH;
    const size_t orow1 = orow0 + (size_t)8 * DM;
    #pragma unroll
    for (int nt = 0; nt < 8; nt++) {
        int col = 8 * nt + tg * 2;
        *(float2*)&g_att[orow0 + col] =
            make_float2(oacc[nt][0] * inv0, oacc[nt][1] * inv0);
        *(float2*)&g_att[orow1 + col] =
            make_float2(oacc[nt][2] * inv1, oacc[nt][3] * inv1);
    }
}

// =====================================================================
extern "C" void kernel_launch(void* const* d_in, const int* in_sizes, int n_in,
                              void* d_out, int out_size)
{
    const float* x        = (const float*)d_in[0];
    const float* coords   = (const float*)d_in[1];
    const unsigned char* mask = (const unsigned char*)d_in[2];
    const float* qkv_w    = (const float*)d_in[3];
    const float* out_w    = (const float*)d_in[4];
    const float* out_b    = (const float*)d_in[5];
    const float* alpha    = (const float*)d_in[6];
    const float* w1       = (const float*)d_in[7];
    const float* b1       = (const float*)d_in[8];
    const float* w2       = (const float*)d_in[9];
    const float* b2       = (const float*)d_in[10];
    const float* cscales  = (const float*)d_in[11];
    float* out            = (float*)d_out;

    cudaFuncSetAttribute(k_gemm_qkv_mma, cudaFuncAttributeMaxDynamicSharedMemorySize,
                         GEMM_SMEM);
    cudaFuncSetAttribute(k_gemm_out_mma, cudaFuncAttributeMaxDynamicSharedMemorySize,
                         GEMM_SMEM);
    cudaFuncSetAttribute(k_attn_mma, cudaFuncAttributeMaxDynamicSharedMemorySize,
                         ATTN_SMEM2);

    // QKV projection (mma.sync split-bf16)
    {
        dim3 grid(QKVD / 128, (B_ * N_) / 128);
        k_gemm_qkv_mma<<<grid, 256, GEMM_SMEM>>>(x, qkv_w);
    }
    // pairwise bias MLP
    {
        dim3 grid(N_ / 32, N_ / 8, B_);
        dim3 blk(32, 8);
        k_bias<<<grid, blk>>>(coords, cscales, w1, b1, w2, b2, alpha);
    }
    // tensor-core flash attention with additive bias
    {
        dim3 grid(N_ / 128, H_, B_);
        k_attn_mma<<<grid, 256, ATTN_SMEM2>>>(mask);
    }
    // output projection (mma.sync split-bf16)
    {
        dim3 grid(DM / 128, (B_ * N_) / 128);
        k_gemm_out_mma<<<grid, 256, GEMM_SMEM>>>(out_w, out_b, out);
    }
}

// round 7
// speedup vs baseline: 1.8226x; 1.1251x over previous
#include <cuda_runtime.h>
#include <cuda_bf16.h>
#include <cstdint>
#include <math.h>

#define B_   8
#define N_   1024
#define DM   512
#define H_   8
#define DH   64
#define QKVD 1536
#define NS_  1
#define SCALE 0.125f

// ---------------- scratch (device globals; no allocations) ----------------
__device__ float g_qkv[(size_t)B_ * N_ * QKVD];        //  50.3 MB  [b][n][3D]
__device__ float g_bias[(size_t)B_ * H_ * N_ * N_];    // 268.4 MB  [b][h][i][j]
__device__ float g_att[(size_t)B_ * N_ * DM];          //  16.8 MB  [b][n][h*64+d]

// =====================================================================
// common helpers
// =====================================================================
#define MMA16816(d, a, b) \
  asm volatile("mma.sync.aligned.m16n8k16.row.col.f32.bf16.bf16.f32 " \
    "{%0,%1,%2,%3}, {%4,%5,%6,%7}, {%8,%9}, {%0,%1,%2,%3};" \
    : "+f"((d)[0]), "+f"((d)[1]), "+f"((d)[2]), "+f"((d)[3]) \
    : "r"((a)[0]), "r"((a)[1]), "r"((a)[2]), "r"((a)[3]), \
      "r"((b)[0]), "r"((b)[1]))

#define LDMX2T(r0, r1, addr) \
  asm volatile("ldmatrix.sync.aligned.m8n8.x2.trans.shared.b16 {%0,%1}, [%2];" \
    : "=r"(r0), "=r"(r1) : "r"(addr))

__device__ __forceinline__ void split2(float a, float b, uint32_t& hi, uint32_t& lo)
{
    __nv_bfloat16 ha = __float2bfloat16(a), hb = __float2bfloat16(b);
    __nv_bfloat16 la = __float2bfloat16(a - __bfloat162float(ha));
    __nv_bfloat16 lb = __float2bfloat16(b - __bfloat162float(hb));
    __nv_bfloat162 h{ha, hb}, l{la, lb};
    hi = *(uint32_t*)&h; lo = *(uint32_t*)&l;
}

__device__ __forceinline__ void split_store(__nv_bfloat16* hp, __nv_bfloat16* lp,
                                            float4 v)
{
    uint32_t h0, l0, h1, l1;
    split2(v.x, v.y, h0, l0);
    split2(v.z, v.w, h1, l1);
    *(uint2*)hp = make_uint2(h0, h1);
    *(uint2*)lp = make_uint2(l0, l1);
}

// fast exp on the FMA pipe (MUFU-free). rel err ~2e-8.
__device__ __forceinline__ float exp_fast(float x)
{
    x = fmaxf(x, -87.0f);
    const float L2E   = 1.4426950408889634f;
    const float MAGIC = 12582912.0f;            // 1.5 * 2^23
    float t = fmaf(x, L2E, MAGIC);
    int   i = __float_as_int(t);
    float n = t - MAGIC;
    float f = fmaf(x, L2E, -n);                 // in [-0.5, 0.5]
    float p = 1.5403530393e-4f;
    p = fmaf(p, f, 1.3333558146e-3f);
    p = fmaf(p, f, 9.6181291076e-3f);
    p = fmaf(p, f, 5.5504108665e-2f);
    p = fmaf(p, f, 2.4022650696e-1f);
    p = fmaf(p, f, 6.9314718056e-1f);
    p = fmaf(p, f, 1.0f);
    return __int_as_float(__float_as_int(p) + (i << 23));
}

// tanh-form GELU on MUFU: gelu(t) = t * sigmoid(2*0.7978845608*(t+0.044715 t^3))
//   = t - t * rcp(ex2(z) + 1),  z = 2.3022074 * t * (1 + 0.044715 t^2)
// 6 FMA-class ops + 2 MUFU; max deviation from exact erf-gelu ~4e-4.
__device__ __forceinline__ float gelu_fast(float t)
{
    float t2 = t * t;
    float in = fmaf(0.044715f, t2, 1.0f);
    float z  = t * in * 2.3022074f;     // 2*sqrt(2/pi)*log2(e)
    float e;
    asm("ex2.approx.f32 %0, %1;" : "=f"(e) : "f"(z));
    float d = e + 1.0f;
    float r;
    asm("rcp.approx.f32 %0, %1;" : "=f"(r) : "f"(d));
    return fmaf(-t, r, t);              // t*(1 - 1/(e^{2y}+1)) = t*sigmoid(2y)
}

// =====================================================================
// mma.sync bf16 GEMM body (R5-proven) — now 2 CTAs/SM via launch bounds
// =====================================================================
#define KC    16
#define LDSB  24
#define PLANE (128 * LDSB)
#define STAGE (4 * PLANE)
#define GEMM_SMEM (2 * STAGE * 2)

__device__ __forceinline__ void gemm_mma_body(
    const float* __restrict__ A, const float* __restrict__ W,
    const float* __restrict__ bias, float* __restrict__ C,
    int Nc, int K)
{
    extern __shared__ __nv_bfloat16 smb[];
    const int tid  = threadIdx.x;
    const int wid  = tid >> 5, lane = tid & 31;
    const int g    = lane >> 2, tg = lane & 3;
    const int m0   = blockIdx.y * 128, n0 = blockIdx.x * 128;
    const int wm   = (wid >> 2) * 64,  wn = (wid & 3) * 32;

    float acc[4][4][4];
    #pragma unroll
    for (int mt = 0; mt < 4; mt++)
        #pragma unroll
        for (int nt = 0; nt < 4; nt++)
            #pragma unroll
            for (int r = 0; r < 4; r++) acc[mt][nt][r] = 0.f;

    const int NCH = K / KC;
    const int prow0 = tid >> 2;
    const int pk4   = (tid & 3) << 2;
    float4 ra[2], rw[2];

    {
        #pragma unroll
        for (int t = 0; t < 2; t++) {
            int row = prow0 + t * 64;
            ra[t] = *(const float4*)&A[(size_t)(m0 + row) * K + pk4];
            rw[t] = *(const float4*)&W[(size_t)(n0 + row) * K + pk4];
        }
        __nv_bfloat16* s = smb;
        #pragma unroll
        for (int t = 0; t < 2; t++) {
            int row = prow0 + t * 64;
            int off = row * LDSB + pk4;
            split_store(s + off,             s + PLANE + off,     ra[t]);
            split_store(s + 2 * PLANE + off, s + 3 * PLANE + off, rw[t]);
        }
    }

    for (int c = 0; c < NCH; c++) {
        __syncthreads();

        if (c + 1 < NCH) {
            const int k0 = (c + 1) * KC;
            #pragma unroll
            for (int t = 0; t < 2; t++) {
                int row = prow0 + t * 64;
                ra[t] = *(const float4*)&A[(size_t)(m0 + row) * K + k0 + pk4];
                rw[t] = *(const float4*)&W[(size_t)(n0 + row) * K + k0 + pk4];
            }
        }

        {
            const __nv_bfloat16* Ah = smb + (c & 1) * STAGE;
            const __nv_bfloat16* Al = Ah + PLANE;
            const __nv_bfloat16* Bh = Ah + 2 * PLANE;
            const __nv_bfloat16* Bl = Ah + 3 * PLANE;

            uint32_t ah[4][4], al[4][4], bh[4][2], bl[4][2];
            #pragma unroll
            for (int mt = 0; mt < 4; mt++) {
                int base = (wm + mt * 16 + g) * LDSB + tg * 2;
                ah[mt][0] = *(const uint32_t*)(Ah + base);
                ah[mt][1] = *(const uint32_t*)(Ah + base + 8 * LDSB);
                ah[mt][2] = *(const uint32_t*)(Ah + base + 8);
                ah[mt][3] = *(const uint32_t*)(Ah + base + 8 * LDSB + 8);
                al[mt][0] = *(const uint32_t*)(Al + base);
                al[mt][1] = *(const uint32_t*)(Al + base + 8 * LDSB);
                al[mt][2] = *(const uint32_t*)(Al + base + 8);
                al[mt][3] = *(const uint32_t*)(Al + base + 8 * LDSB + 8);
            }
            #pragma unroll
            for (int nt = 0; nt < 4; nt++) {
                int base = (wn + nt * 8 + g) * LDSB + tg * 2;
                bh[nt][0] = *(const uint32_t*)(Bh + base);
                bh[nt][1] = *(const uint32_t*)(Bh + base + 8);
                bl[nt][0] = *(const uint32_t*)(Bl + base);
                bl[nt][1] = *(const uint32_t*)(Bl + base + 8);
            }
            #pragma unroll
            for (int mt = 0; mt < 4; mt++)
                #pragma unroll
                for (int nt = 0; nt < 4; nt++)
                    MMA16816(acc[mt][nt], ah[mt], bh[nt]);
            #pragma unroll
            for (int mt = 0; mt < 4; mt++)
                #pragma unroll
                for (int nt = 0; nt < 4; nt++)
                    MMA16816(acc[mt][nt], al[mt], bh[nt]);
            #pragma unroll
            for (int mt = 0; mt < 4; mt++)
                #pragma unroll
                for (int nt = 0; nt < 4; nt++)
                    MMA16816(acc[mt][nt], ah[mt], bl[nt]);
        }

        if (c + 1 < NCH) {
            __nv_bfloat16* s = smb + ((c + 1) & 1) * STAGE;
            #pragma unroll
            for (int t = 0; t < 2; t++) {
                int row = prow0 + t * 64;
                int off = row * LDSB + pk4;
                split_store(s + off,             s + PLANE + off,     ra[t]);
                split_store(s + 2 * PLANE + off, s + 3 * PLANE + off, rw[t]);
            }
        }
    }

    #pragma unroll
    for (int mt = 0; mt < 4; mt++) {
        #pragma unroll
        for (int nt = 0; nt < 4; nt++) {
            int row = m0 + wm + mt * 16 + g;
            int col = n0 + wn + nt * 8 + tg * 2;
            float bx = 0.f, by = 0.f;
            if (bias) { bx = bias[col]; by = bias[col + 1]; }
            *(float2*)&C[(size_t)row * Nc + col] =
                make_float2(acc[mt][nt][0] + bx, acc[mt][nt][1] + by);
            *(float2*)&C[(size_t)(row + 8) * Nc + col] =
                make_float2(acc[mt][nt][2] + bx, acc[mt][nt][3] + by);
        }
    }
}

__global__ void __launch_bounds__(256, 2)
k_gemm_qkv_mma(const float* __restrict__ x, const float* __restrict__ qkv_w)
{
    gemm_mma_body(x, qkv_w, nullptr, g_qkv, QKVD, DM);
}

__global__ void __launch_bounds__(256, 2)
k_gemm_out_mma(const float* __restrict__ out_w, const float* __restrict__ out_b,
               float* __restrict__ out)
{
    gemm_mma_body(g_att, out_w, out_b, out, DM, DM);
}

// =====================================================================
// Pairwise bias MLP — MUFU-based gelu, reciprocal coord scales
// =====================================================================
__global__ void __launch_bounds__(256)
k_bias(const float* __restrict__ coords, const float* __restrict__ cs,
       const float* __restrict__ w1, const float* __restrict__ b1,
       const float* __restrict__ w2, const float* __restrict__ b2,
       const float* __restrict__ alpha_p)
{
    __shared__ float sw1[32][4];
    __shared__ float sb1[32];
    __shared__ float sw2[8][32];
    __shared__ float sb2[8];
    __shared__ float sinv[3];
    __shared__ float salpha;

    const int tid = threadIdx.y * 32 + threadIdx.x;
    if (tid < 128) ((float*)sw1)[tid] = w1[tid];
    if (tid < 256) ((float*)sw2)[tid] = w2[tid];
    if (tid < 32)  sb1[tid] = b1[tid];
    if (tid < 8)   sb2[tid] = b2[tid];
    if (tid < 3)   sinv[tid] = 1.0f / cs[tid];
    if (tid == 0)  salpha = alpha_p[0];
    __syncthreads();

    const int b = blockIdx.z;
    const int i = blockIdx.y * 8 + threadIdx.y;
    const int j = blockIdx.x * 32 + threadIdx.x;

    float out[8];
    #pragma unroll
    for (int h = 0; h < 8; h++) out[h] = 0.f;

    if (i >= NS_ && j >= NS_) {
        const float* ci = &coords[((size_t)b * N_ + i) * 3];
        const float* cj = &coords[((size_t)b * N_ + j) * 3];
        float dx = (ci[0] - cj[0]) * sinv[0];
        float dy = (ci[1] - cj[1]) * sinv[1];
        float dz = (ci[2] - cj[2]) * sinv[2];
        float dist = sqrtf(fmaf(dx, dx, fmaf(dy, dy, dz * dz)));

        #pragma unroll
        for (int h = 0; h < 8; h++) out[h] = sb2[h];

        #pragma unroll 8
        for (int k = 0; k < 32; k++) {
            float t = fmaf(sw1[k][0], dx,
                      fmaf(sw1[k][1], dy,
                      fmaf(sw1[k][2], dz,
                      fmaf(sw1[k][3], dist, sb1[k]))));
            float g = gelu_fast(t);
            #pragma unroll
            for (int h = 0; h < 8; h++)
                out[h] = fmaf(sw2[h][k], g, out[h]);
        }
    }

    const size_t base = ((size_t)b * H_ * N_ + i) * N_ + j;
    #pragma unroll
    for (int h = 0; h < 8; h++)
        g_bias[base + (size_t)h * N_ * N_] = salpha * out[h];
}

// =====================================================================
// Tensor-core flash attention (R6-proven, unchanged)
// =====================================================================
#define LQ 72
#define ATTN_SMEM2 (36864 * 2 + 64 * 4)

__global__ void __launch_bounds__(256)
k_attn_mma(const unsigned char* __restrict__ mask)
{
    extern __shared__ __nv_bfloat16 sma[];
    __nv_bfloat16* Qh = sma;
    __nv_bfloat16* Ql = sma + 9216;
    __nv_bfloat16* Kh = sma + 18432;
    __nv_bfloat16* Kl = sma + 23040;
    __nv_bfloat16* Vh = sma + 27648;
    __nv_bfloat16* Vl = sma + 32256;
    float* madd = (float*)(sma + 36864);

    const int b = blockIdx.z, h = blockIdx.y;
    const int i0 = blockIdx.x * 128;
    const int tid = threadIdx.x;
    const int w = tid >> 5, lane = tid & 31;
    const int g = lane >> 2, tg = lane & 3;

    const uint32_t vh_u32 = (uint32_t)__cvta_generic_to_shared(Vh);
    const uint32_t vl_u32 = (uint32_t)__cvta_generic_to_shared(Vl);

    #pragma unroll
    for (int t = 0; t < 8; t++) {
        int f = tid + t * 256;
        int row = f >> 4;
        int c4 = (f & 15) << 2;
        float4 v = *(const float4*)&g_qkv[((size_t)(b * N_ + i0 + row)) * QKVD + h * DH + c4];
        split_store(Qh + row * LQ + c4, Ql + row * LQ + c4, v);
    }

    float oacc[8][4];
    #pragma unroll
    for (int nt = 0; nt < 8; nt++)
        #pragma unroll
        for (int r = 0; r < 4; r++) oacc[nt][r] = 0.f;
    float m0r = -INFINITY, m1r = -INFINITY, l0r = 0.f, l1r = 0.f;

    const size_t bias_row0 = ((size_t)(b * H_ + h) * N_ + (i0 + w * 16 + g)) * N_;
    const int qrow = (w * 16 + g) * LQ + tg * 2;

    for (int j0 = 0; j0 < N_; j0 += 64) {
        __syncthreads();

        #pragma unroll
        for (int t = 0; t < 4; t++) {
            int f = tid + t * 256;
            int row = f >> 4;
            int c4 = (f & 15) << 2;
            size_t rb = ((size_t)(b * N_ + j0 + row)) * QKVD + h * DH + c4;
            float4 kv = *(const float4*)&g_qkv[rb + DM];
            split_store(Kh + row * LQ + c4, Kl + row * LQ + c4, kv);
            float4 vv = *(const float4*)&g_qkv[rb + 2 * DM];
            split_store(Vh + row * LQ + c4, Vl + row * LQ + c4, vv);
        }
        if (tid < 64)
            madd[tid] = mask[(size_t)b * N_ + j0 + tid] ? -1e30f : 0.0f;
        __syncthreads();

        float sacc[8][4];
        #pragma unroll
        for (int nt = 0; nt < 8; nt++)
            #pragma unroll
            for (int r = 0; r < 4; r++) sacc[nt][r] = 0.f;

        #pragma unroll
        for (int kc = 0; kc < 4; kc++) {
            int qb = qrow + kc * 16;
            uint32_t qh[4], ql[4];
            qh[0] = *(const uint32_t*)(Qh + qb);
            qh[1] = *(const uint32_t*)(Qh + qb + 8 * LQ);
            qh[2] = *(const uint32_t*)(Qh + qb + 8);
            qh[3] = *(const uint32_t*)(Qh + qb + 8 * LQ + 8);
            ql[0] = *(const uint32_t*)(Ql + qb);
            ql[1] = *(const uint32_t*)(Ql + qb + 8 * LQ);
            ql[2] = *(const uint32_t*)(Ql + qb + 8);
            ql[3] = *(const uint32_t*)(Ql + qb + 8 * LQ + 8);
            #pragma unroll
            for (int nt = 0; nt < 8; nt++) {
                int kb = (8 * nt + g) * LQ + kc * 16 + tg * 2;
                uint32_t bh[2], bl[2];
                bh[0] = *(const uint32_t*)(Kh + kb);
                bh[1] = *(const uint32_t*)(Kh + kb + 8);
                bl[0] = *(const uint32_t*)(Kl + kb);
                bl[1] = *(const uint32_t*)(Kl + kb + 8);
                MMA16816(sacc[nt], qh, bh);
                MMA16816(sacc[nt], ql, bh);
                MMA16816(sacc[nt], qh, bl);
            }
        }

        const float* bp0 = &g_bias[bias_row0 + j0];
        const float* bp1 = bp0 + 8 * N_;
        #pragma unroll
        for (int nt = 0; nt < 8; nt++) {
            int col = 8 * nt + tg * 2;
            float2 mz = *(float2*)&madd[col];
            float2 bz0 = *(const float2*)&bp0[col];
            float2 bz1 = *(const float2*)&bp1[col];
            sacc[nt][0] = fmaf(sacc[nt][0], SCALE, bz0.x) + mz.x;
            sacc[nt][1] = fmaf(sacc[nt][1], SCALE, bz0.y) + mz.y;
            sacc[nt][2] = fmaf(sacc[nt][2], SCALE, bz1.x) + mz.x;
            sacc[nt][3] = fmaf(sacc[nt][3], SCALE, bz1.y) + mz.y;
        }

        float mx0 = -INFINITY, mx1 = -INFINITY;
        #pragma unroll
        for (int nt = 0; nt < 8; nt++) {
            mx0 = fmaxf(mx0, fmaxf(sacc[nt][0], sacc[nt][1]));
            mx1 = fmaxf(mx1, fmaxf(sacc[nt][2], sacc[nt][3]));
        }
        mx0 = fmaxf(mx0, __shfl_xor_sync(0xffffffffu, mx0, 1));
        mx0 = fmaxf(mx0, __shfl_xor_sync(0xffffffffu, mx0, 2));
        mx1 = fmaxf(mx1, __shfl_xor_sync(0xffffffffu, mx1, 1));
        mx1 = fmaxf(mx1, __shfl_xor_sync(0xffffffffu, mx1, 2));

        float mn0 = fmaxf(m0r, mx0), mn1 = fmaxf(m1r, mx1);
        float a0 = exp_fast(m0r - mn0), a1 = exp_fast(m1r - mn1);
        m0r = mn0; m1r = mn1;

        float rs0 = 0.f, rs1 = 0.f;
        #pragma unroll
        for (int nt = 0; nt < 8; nt++) {
            float p0 = exp_fast(sacc[nt][0] - mn0);
            float p1 = exp_fast(sacc[nt][1] - mn0);
            float p2 = exp_fast(sacc[nt][2] - mn1);
            float p3 = exp_fast(sacc[nt][3] - mn1);
            sacc[nt][0] = p0; sacc[nt][1] = p1;
            sacc[nt][2] = p2; sacc[nt][3] = p3;
            rs0 += p0 + p1; rs1 += p2 + p3;
        }
        rs0 += __shfl_xor_sync(0xffffffffu, rs0, 1);
        rs0 += __shfl_xor_sync(0xffffffffu, rs0, 2);
        rs1 += __shfl_xor_sync(0xffffffffu, rs1, 1);
        rs1 += __shfl_xor_sync(0xffffffffu, rs1, 2);
        l0r = l0r * a0 + rs0;
        l1r = l1r * a1 + rs1;
        #pragma unroll
        for (int nt = 0; nt < 8; nt++) {
            oacc[nt][0] *= a0; oacc[nt][1] *= a0;
            oacc[nt][2] *= a1; oacc[nt][3] *= a1;
        }

        #pragma unroll
        for (int kc = 0; kc < 4; kc++) {
            uint32_t ph[4], pl[4];
            split2(sacc[2 * kc][0],     sacc[2 * kc][1],     ph[0], pl[0]);
            split2(sacc[2 * kc][2],     sacc[2 * kc][3],     ph[1], pl[1]);
            split2(sacc[2 * kc + 1][0], sacc[2 * kc + 1][1], ph[2], pl[2]);
            split2(sacc[2 * kc + 1][2], sacc[2 * kc + 1][3], ph[3], pl[3]);

            uint32_t rowoff = (uint32_t)((16 * kc + (lane & 15)) * LQ) * 2;
            #pragma unroll
            for (int ntd = 0; ntd < 8; ntd++) {
                uint32_t bh[2], bl[2];
                LDMX2T(bh[0], bh[1], vh_u32 + rowoff + ntd * 16);
                LDMX2T(bl[0], bl[1], vl_u32 + rowoff + ntd * 16);
                MMA16816(oacc[ntd], ph, bh);
                MMA16816(oacc[ntd], pl, bh);
                MMA16816(oacc[ntd], ph, bl);
            }
        }
    }

    float inv0 = 1.0f / l0r, inv1 = 1.0f / l1r;
    const size_t orow0 = ((size_t)(b * N_ + i0 + w * 16 + g)) * DM + h * DH;
    const size_t orow1 = orow0 + (size_t)8 * DM;
    #pragma unroll
    for (int nt = 0; nt < 8; nt++) {
        int col = 8 * nt + tg * 2;
        *(float2*)&g_att[orow0 + col] =
            make_float2(oacc[nt][0] * inv0, oacc[nt][1] * inv0);
        *(float2*)&g_att[orow1 + col] =
            make_float2(oacc[nt][2] * inv1, oacc[nt][3] * inv1);
    }
}

// =====================================================================
extern "C" void kernel_launch(void* const* d_in, const int* in_sizes, int n_in,
                              void* d_out, int out_size)
{
    const float* x        = (const float*)d_in[0];
    const float* coords   = (const float*)d_in[1];
    const unsigned char* mask = (const unsigned char*)d_in[2];
    const float* qkv_w    = (const float*)d_in[3];
    const float* out_w    = (const float*)d_in[4];
    const float* out_b    = (const float*)d_in[5];
    const float* alpha    = (const float*)d_in[6];
    const float* w1       = (const float*)d_in[7];
    const float* b1       = (const float*)d_in[8];
    const float* w2       = (const float*)d_in[9];
    const float* b2       = (const float*)d_in[10];
    const float* cscales  = (const float*)d_in[11];
    float* out            = (float*)d_out;

    cudaFuncSetAttribute(k_gemm_qkv_mma, cudaFuncAttributeMaxDynamicSharedMemorySize,
                         GEMM_SMEM);
    cudaFuncSetAttribute(k_gemm_out_mma, cudaFuncAttributeMaxDynamicSharedMemorySize,
                         GEMM_SMEM);
    cudaFuncSetAttribute(k_attn_mma, cudaFuncAttributeMaxDynamicSharedMemorySize,
                         ATTN_SMEM2);

    // QKV projection (mma.sync split-bf16)
    {
        dim3 grid(QKVD / 128, (B_ * N_) / 128);
        k_gemm_qkv_mma<<<grid, 256, GEMM_SMEM>>>(x, qkv_w);
    }
    // pairwise bias MLP
    {
        dim3 grid(N_ / 32, N_ / 8, B_);
        dim3 blk(32, 8);
        k_bias<<<grid, blk>>>(coords, cscales, w1, b1, w2, b2, alpha);
    }
    // tensor-core flash attention with additive bias
    {
        dim3 grid(N_ / 128, H_, B_);
        k_attn_mma<<<grid, 256, ATTN_SMEM2>>>(mask);
    }
    // output projection (mma.sync split-bf16)
    {
        dim3 grid(DM / 128, (B_ * N_) / 128);
        k_gemm_out_mma<<<grid, 256, GEMM_SMEM>>>(out_w, out_b, out);
    }
}

// round 8
// speedup vs baseline: 1.9950x; 1.0946x over previous
#include <cuda_runtime.h>
#include <cuda_bf16.h>
#include <cstdint>
#include <math.h>

#define B_   8
#define N_   1024
#define DM   512
#define H_   8
#define DH   64
#define QKVD 1536
#define NS_  1
#define SCALE 0.125f

// ---------------- scratch (device globals; no allocations) ----------------
__device__ float g_qkv[(size_t)B_ * N_ * QKVD];        //  50.3 MB  [b][n][3D]
__device__ float g_bias[(size_t)B_ * H_ * N_ * N_];    // 268.4 MB  [b][h][i][j]
__device__ float g_att[(size_t)B_ * N_ * DM];          //  16.8 MB  [b][n][h*64+d]

// =====================================================================
// common helpers
// =====================================================================
#define MMA16816(d, a, b) \
  asm volatile("mma.sync.aligned.m16n8k16.row.col.f32.bf16.bf16.f32 " \
    "{%0,%1,%2,%3}, {%4,%5,%6,%7}, {%8,%9}, {%0,%1,%2,%3};" \
    : "+f"((d)[0]), "+f"((d)[1]), "+f"((d)[2]), "+f"((d)[3]) \
    : "r"((a)[0]), "r"((a)[1]), "r"((a)[2]), "r"((a)[3]), \
      "r"((b)[0]), "r"((b)[1]))

#define LDMX2T(r0, r1, addr) \
  asm volatile("ldmatrix.sync.aligned.m8n8.x2.trans.shared.b16 {%0,%1}, [%2];" \
    : "=r"(r0), "=r"(r1) : "r"(addr))

__device__ __forceinline__ void split2(float a, float b, uint32_t& hi, uint32_t& lo)
{
    __nv_bfloat16 ha = __float2bfloat16(a), hb = __float2bfloat16(b);
    __nv_bfloat16 la = __float2bfloat16(a - __bfloat162float(ha));
    __nv_bfloat16 lb = __float2bfloat16(b - __bfloat162float(hb));
    __nv_bfloat162 h{ha, hb}, l{la, lb};
    hi = *(uint32_t*)&h; lo = *(uint32_t*)&l;
}

__device__ __forceinline__ void split_store(__nv_bfloat16* hp, __nv_bfloat16* lp,
                                            float4 v)
{
    uint32_t h0, l0, h1, l1;
    split2(v.x, v.y, h0, l0);
    split2(v.z, v.w, h1, l1);
    *(uint2*)hp = make_uint2(h0, h1);
    *(uint2*)lp = make_uint2(l0, l1);
}

// fast exp on the FMA pipe (MUFU-free). rel err ~2e-8.
__device__ __forceinline__ float exp_fast(float x)
{
    x = fmaxf(x, -87.0f);
    const float L2E   = 1.4426950408889634f;
    const float MAGIC = 12582912.0f;            // 1.5 * 2^23
    float t = fmaf(x, L2E, MAGIC);
    int   i = __float_as_int(t);
    float n = t - MAGIC;
    float f = fmaf(x, L2E, -n);                 // in [-0.5, 0.5]
    float p = 1.5403530393e-4f;
    p = fmaf(p, f, 1.3333558146e-3f);
    p = fmaf(p, f, 9.6181291076e-3f);
    p = fmaf(p, f, 5.5504108665e-2f);
    p = fmaf(p, f, 2.4022650696e-1f);
    p = fmaf(p, f, 6.9314718056e-1f);
    p = fmaf(p, f, 1.0f);
    return __int_as_float(__float_as_int(p) + (i << 23));
}

// tanh-form GELU, single MUFU (tanh.approx): 4 FMA-class + 1 MUFU.
__device__ __forceinline__ float gelu_tanh(float t)
{
    float t2 = t * t;
    float u  = fmaf(0.0356774081f, t2, 0.7978845608f);  // sqrt(2/pi)*(1+0.044715 t^2)
    float z  = t * u;
    float th;
    asm("tanh.approx.f32 %0, %1;" : "=f"(th) : "f"(z));
    float ht = 0.5f * t;
    return fmaf(ht, th, ht);
}

// =====================================================================
// mma.sync bf16 GEMM body (R5-proven, unchanged)
// =====================================================================
#define KC    16
#define LDSB  24
#define PLANE (128 * LDSB)
#define STAGE (4 * PLANE)
#define GEMM_SMEM (2 * STAGE * 2)

__device__ __forceinline__ void gemm_mma_body(
    const float* __restrict__ A, const float* __restrict__ W,
    const float* __restrict__ bias, float* __restrict__ C,
    int Nc, int K)
{
    extern __shared__ __nv_bfloat16 smb[];
    const int tid  = threadIdx.x;
    const int wid  = tid >> 5, lane = tid & 31;
    const int g    = lane >> 2, tg = lane & 3;
    const int m0   = blockIdx.y * 128, n0 = blockIdx.x * 128;
    const int wm   = (wid >> 2) * 64,  wn = (wid & 3) * 32;

    float acc[4][4][4];
    #pragma unroll
    for (int mt = 0; mt < 4; mt++)
        #pragma unroll
        for (int nt = 0; nt < 4; nt++)
            #pragma unroll
            for (int r = 0; r < 4; r++) acc[mt][nt][r] = 0.f;

    const int NCH = K / KC;
    const int prow0 = tid >> 2;
    const int pk4   = (tid & 3) << 2;
    float4 ra[2], rw[2];

    {
        #pragma unroll
        for (int t = 0; t < 2; t++) {
            int row = prow0 + t * 64;
            ra[t] = *(const float4*)&A[(size_t)(m0 + row) * K + pk4];
            rw[t] = *(const float4*)&W[(size_t)(n0 + row) * K + pk4];
        }
        __nv_bfloat16* s = smb;
        #pragma unroll
        for (int t = 0; t < 2; t++) {
            int row = prow0 + t * 64;
            int off = row * LDSB + pk4;
            split_store(s + off,             s + PLANE + off,     ra[t]);
            split_store(s + 2 * PLANE + off, s + 3 * PLANE + off, rw[t]);
        }
    }

    for (int c = 0; c < NCH; c++) {
        __syncthreads();

        if (c + 1 < NCH) {
            const int k0 = (c + 1) * KC;
            #pragma unroll
            for (int t = 0; t < 2; t++) {
                int row = prow0 + t * 64;
                ra[t] = *(const float4*)&A[(size_t)(m0 + row) * K + k0 + pk4];
                rw[t] = *(const float4*)&W[(size_t)(n0 + row) * K + k0 + pk4];
            }
        }

        {
            const __nv_bfloat16* Ah = smb + (c & 1) * STAGE;
            const __nv_bfloat16* Al = Ah + PLANE;
            const __nv_bfloat16* Bh = Ah + 2 * PLANE;
            const __nv_bfloat16* Bl = Ah + 3 * PLANE;

            uint32_t ah[4][4], al[4][4], bh[4][2], bl[4][2];
            #pragma unroll
            for (int mt = 0; mt < 4; mt++) {
                int base = (wm + mt * 16 + g) * LDSB + tg * 2;
                ah[mt][0] = *(const uint32_t*)(Ah + base);
                ah[mt][1] = *(const uint32_t*)(Ah + base + 8 * LDSB);
                ah[mt][2] = *(const uint32_t*)(Ah + base + 8);
                ah[mt][3] = *(const uint32_t*)(Ah + base + 8 * LDSB + 8);
                al[mt][0] = *(const uint32_t*)(Al + base);
                al[mt][1] = *(const uint32_t*)(Al + base + 8 * LDSB);
                al[mt][2] = *(const uint32_t*)(Al + base + 8);
                al[mt][3] = *(const uint32_t*)(Al + base + 8 * LDSB + 8);
            }
            #pragma unroll
            for (int nt = 0; nt < 4; nt++) {
                int base = (wn + nt * 8 + g) * LDSB + tg * 2;
                bh[nt][0] = *(const uint32_t*)(Bh + base);
                bh[nt][1] = *(const uint32_t*)(Bh + base + 8);
                bl[nt][0] = *(const uint32_t*)(Bl + base);
                bl[nt][1] = *(const uint32_t*)(Bl + base + 8);
            }
            #pragma unroll
            for (int mt = 0; mt < 4; mt++)
                #pragma unroll
                for (int nt = 0; nt < 4; nt++)
                    MMA16816(acc[mt][nt], ah[mt], bh[nt]);
            #pragma unroll
            for (int mt = 0; mt < 4; mt++)
                #pragma unroll
                for (int nt = 0; nt < 4; nt++)
                    MMA16816(acc[mt][nt], al[mt], bh[nt]);
            #pragma unroll
            for (int mt = 0; mt < 4; mt++)
                #pragma unroll
                for (int nt = 0; nt < 4; nt++)
                    MMA16816(acc[mt][nt], ah[mt], bl[nt]);
        }

        if (c + 1 < NCH) {
            __nv_bfloat16* s = smb + ((c + 1) & 1) * STAGE;
            #pragma unroll
            for (int t = 0; t < 2; t++) {
                int row = prow0 + t * 64;
                int off = row * LDSB + pk4;
                split_store(s + off,             s + PLANE + off,     ra[t]);
                split_store(s + 2 * PLANE + off, s + 3 * PLANE + off, rw[t]);
            }
        }
    }

    #pragma unroll
    for (int mt = 0; mt < 4; mt++) {
        #pragma unroll
        for (int nt = 0; nt < 4; nt++) {
            int row = m0 + wm + mt * 16 + g;
            int col = n0 + wn + nt * 8 + tg * 2;
            float bx = 0.f, by = 0.f;
            if (bias) { bx = bias[col]; by = bias[col + 1]; }
            *(float2*)&C[(size_t)row * Nc + col] =
                make_float2(acc[mt][nt][0] + bx, acc[mt][nt][1] + by);
            *(float2*)&C[(size_t)(row + 8) * Nc + col] =
                make_float2(acc[mt][nt][2] + bx, acc[mt][nt][3] + by);
        }
    }
}

__global__ void __launch_bounds__(256, 2)
k_gemm_qkv_mma(const float* __restrict__ x, const float* __restrict__ qkv_w)
{
    gemm_mma_body(x, qkv_w, nullptr, g_qkv, QKVD, DM);
}

__global__ void __launch_bounds__(256, 2)
k_gemm_out_mma(const float* __restrict__ out_w, const float* __restrict__ out_b,
               float* __restrict__ out)
{
    gemm_mma_body(g_att, out_w, out_b, out, DM, DM);
}

// =====================================================================
// Pairwise bias MLP — BOTH layers on tensor cores.
// Grid (N/128 j-tiles, N/8 i-groups, B). 256 thr = 8 warps; warp tile =
// 16 j-pairs; CTA loops 8 i values. Layer1: K=4 (zero-padded to 16),
// layer1 C-frag == layer2 A-frag (in-register gelu, no movement).
// =====================================================================
__global__ void __launch_bounds__(256)
k_bias_mma(const float* __restrict__ coords, const float* __restrict__ cs,
           const float* __restrict__ w1, const float* __restrict__ b1,
           const float* __restrict__ w2, const float* __restrict__ b2,
           const float* __restrict__ alpha_p)
{
    __shared__ float sj[128 * 3];     // scaled j-coords
    __shared__ float sci[8 * 3];      // scaled i-coords
    __shared__ float sw1[128];        // w1[32][4]
    __shared__ float sb1[32];
    __shared__ float sw2[256];        // w2[8][32]
    __shared__ float sb2[8];
    __shared__ float sinv[3];
    __shared__ float salpha;

    const int tid = threadIdx.x;
    const int w = tid >> 5, lane = tid & 31;
    const int g = lane >> 2, tg = lane & 3;
    const int b = blockIdx.z;
    const int j0 = blockIdx.x * 128;
    const int i0 = blockIdx.y * 8;

    if (tid < 3) sinv[tid] = 1.0f / cs[tid];
    if (tid < 128) sw1[tid] = w1[tid];
    if (tid >= 128 && tid < 160) sb1[tid - 128] = b1[tid - 128];
    if (tid >= 160 && tid < 168) sb2[tid - 160] = b2[tid - 160];
    if (tid == 168) salpha = alpha_p[0];
    __syncthreads();
    for (int idx = tid; idx < 384; idx += 256) {
        int r = idx / 3, c = idx - r * 3;
        sj[idx] = coords[((size_t)(b * N_ + j0 + r)) * 3 + c] * sinv[c];
    }
    if (tid < 24) {
        int r = tid / 3, c = tid - r * 3;
        sci[tid] = coords[((size_t)(b * N_ + i0 + r)) * 3 + c] * sinv[c];
    }
    if (tid < 256) sw2[tid] = w2[tid];
    __syncthreads();

    // ---- constant B-fragments (per thread) ----
    // layer1: B = w1 [n=32 kouts pad-K16]; b[1] (k>=8) is always 0 (K real = 4)
    uint32_t bw1h[4][2], bw1l[4][2];
    #pragma unroll
    for (int nt = 0; nt < 4; nt++) {
        float x0 = 0.f, x1 = 0.f;
        if (tg < 2) {
            x0 = sw1[(nt * 8 + g) * 4 + 2 * tg];
            x1 = sw1[(nt * 8 + g) * 4 + 2 * tg + 1];
        }
        split2(x0, x1, bw1h[nt][0], bw1l[nt][0]);
        bw1h[nt][1] = 0u; bw1l[nt][1] = 0u;
    }
    // layer2: B = w2 [n=8 heads, K=32 in 2 chunks]
    uint32_t bw2h[2][2], bw2l[2][2];
    #pragma unroll
    for (int kc = 0; kc < 2; kc++) {
        split2(sw2[g * 32 + 16 * kc + 2 * tg],
               sw2[g * 32 + 16 * kc + 2 * tg + 1], bw2h[kc][0], bw2l[kc][0]);
        split2(sw2[g * 32 + 16 * kc + 2 * tg + 8],
               sw2[g * 32 + 16 * kc + 2 * tg + 9], bw2h[kc][1], bw2l[kc][1]);
    }

    const int jlA = w * 16 + g;        // local j of pair row g
    const int jlB = jlA + 8;           // local j of pair row g+8
    const float cjAx = sj[jlA * 3], cjAy = sj[jlA * 3 + 1], cjAz = sj[jlA * 3 + 2];
    const float cjBx = sj[jlB * 3], cjBy = sj[jlB * 3 + 1], cjBz = sj[jlB * 3 + 2];
    const int jA = j0 + jlA, jB = j0 + jlB;
    const int h0 = 2 * tg, h1 = h0 + 1;
    const float bh0 = sb2[h0], bh1 = sb2[h1];

    #pragma unroll
    for (int ii = 0; ii < 8; ii++) {
        const int i = i0 + ii;
        const float cix = sci[ii * 3], ciy = sci[ii * 3 + 1], ciz = sci[ii * 3 + 2];

        float dxA = cix - cjAx, dyA = ciy - cjAy, dzA = ciz - cjAz;
        float dsA = sqrtf(fmaf(dxA, dxA, fmaf(dyA, dyA, dzA * dzA)));
        float dxB = cix - cjBx, dyB = ciy - cjBy, dzB = ciz - cjBz;
        float dsB = sqrtf(fmaf(dxB, dxB, fmaf(dyB, dyB, dzB * dzB)));

        // A fragment: feat (K=4 padded) — tg0 carries (dx,dy), tg1 (dz,dist)
        float vA0 = tg == 0 ? dxA : (tg == 1 ? dzA : 0.f);
        float vA1 = tg == 0 ? dyA : (tg == 1 ? dsA : 0.f);
        float vB0 = tg == 0 ? dxB : (tg == 1 ? dzB : 0.f);
        float vB1 = tg == 0 ? dyB : (tg == 1 ? dsB : 0.f);
        uint32_t afh[4], afl[4];
        split2(vA0, vA1, afh[0], afl[0]);
        split2(vB0, vB1, afh[1], afl[1]);
        afh[2] = afh[3] = afl[2] = afl[3] = 0u;

        // layer1 (4 n-tiles x 3 passes)
        float d1[4][4];
        #pragma unroll
        for (int nt = 0; nt < 4; nt++) {
            d1[nt][0] = d1[nt][1] = d1[nt][2] = d1[nt][3] = 0.f;
            MMA16816(d1[nt], afh, bw1h[nt]);
            MMA16816(d1[nt], afl, bw1h[nt]);
            MMA16816(d1[nt], afh, bw1l[nt]);
        }

        // + b1, gelu (in register; C-frag layout == next A-frag layout)
        float gv[4][4];
        #pragma unroll
        for (int nt = 0; nt < 4; nt++) {
            float ba = sb1[8 * nt + 2 * tg], bb = sb1[8 * nt + 2 * tg + 1];
            gv[nt][0] = gelu_tanh(d1[nt][0] + ba);
            gv[nt][1] = gelu_tanh(d1[nt][1] + bb);
            gv[nt][2] = gelu_tanh(d1[nt][2] + ba);
            gv[nt][3] = gelu_tanh(d1[nt][3] + bb);
        }

        // layer2 (K=32: 2 chunks x 3 passes)
        float d2[4] = {0.f, 0.f, 0.f, 0.f};
        #pragma unroll
        for (int kc = 0; kc < 2; kc++) {
            uint32_t a2h[4], a2l[4];
            split2(gv[2 * kc][0],     gv[2 * kc][1],     a2h[0], a2l[0]);
            split2(gv[2 * kc][2],     gv[2 * kc][3],     a2h[1], a2l[1]);
            split2(gv[2 * kc + 1][0], gv[2 * kc + 1][1], a2h[2], a2l[2]);
            split2(gv[2 * kc + 1][2], gv[2 * kc + 1][3], a2h[3], a2l[3]);
            MMA16816(d2, a2h, bw2h[kc]);
            MMA16816(d2, a2l, bw2h[kc]);
            MMA16816(d2, a2h, bw2l[kc]);
        }

        // masks + store: D[pair g][h0,h1], D[pair g+8][h0,h1]
        float si = (i >= NS_) ? salpha : 0.f;
        float sA = (jA >= NS_) ? si : 0.f;
        float sB = si;                       // jB >= 8 always
        size_t r0 = ((size_t)(b * H_ + h0) * N_ + i) * N_;
        size_t r1 = ((size_t)(b * H_ + h1) * N_ + i) * N_;
        g_bias[r0 + jA] = sA * (d2[0] + bh0);
        g_bias[r1 + jA] = sA * (d2[1] + bh1);
        g_bias[r0 + jB] = sB * (d2[2] + bh0);
        g_bias[r1 + jB] = sB * (d2[3] + bh1);
    }
}

// =====================================================================
// Tensor-core flash attention (R6-proven, unchanged)
// =====================================================================
#define LQ 72
#define ATTN_SMEM2 (36864 * 2 + 64 * 4)

__global__ void __launch_bounds__(256)
k_attn_mma(const unsigned char* __restrict__ mask)
{
    extern __shared__ __nv_bfloat16 sma[];
    __nv_bfloat16* Qh = sma;
    __nv_bfloat16* Ql = sma + 9216;
    __nv_bfloat16* Kh = sma + 18432;
    __nv_bfloat16* Kl = sma + 23040;
    __nv_bfloat16* Vh = sma + 27648;
    __nv_bfloat16* Vl = sma + 32256;
    float* madd = (float*)(sma + 36864);

    const int b = blockIdx.z, h = blockIdx.y;
    const int i0 = blockIdx.x * 128;
    const int tid = threadIdx.x;
    const int w = tid >> 5, lane = tid & 31;
    const int g = lane >> 2, tg = lane & 3;

    const uint32_t vh_u32 = (uint32_t)__cvta_generic_to_shared(Vh);
    const uint32_t vl_u32 = (uint32_t)__cvta_generic_to_shared(Vl);

    #pragma unroll
    for (int t = 0; t < 8; t++) {
        int f = tid + t * 256;
        int row = f >> 4;
        int c4 = (f & 15) << 2;
        float4 v = *(const float4*)&g_qkv[((size_t)(b * N_ + i0 + row)) * QKVD + h * DH + c4];
        split_store(Qh + row * LQ + c4, Ql + row * LQ + c4, v);
    }

    float oacc[8][4];
    #pragma unroll
    for (int nt = 0; nt < 8; nt++)
        #pragma unroll
        for (int r = 0; r < 4; r++) oacc[nt][r] = 0.f;
    float m0r = -INFINITY, m1r = -INFINITY, l0r = 0.f, l1r = 0.f;

    const size_t bias_row0 = ((size_t)(b * H_ + h) * N_ + (i0 + w * 16 + g)) * N_;
    const int qrow = (w * 16 + g) * LQ + tg * 2;

    for (int j0 = 0; j0 < N_; j0 += 64) {
        __syncthreads();

        #pragma unroll
        for (int t = 0; t < 4; t++) {
            int f = tid + t * 256;
            int row = f >> 4;
            int c4 = (f & 15) << 2;
            size_t rb = ((size_t)(b * N_ + j0 + row)) * QKVD + h * DH + c4;
            float4 kv = *(const float4*)&g_qkv[rb + DM];
            split_store(Kh + row * LQ + c4, Kl + row * LQ + c4, kv);
            float4 vv = *(const float4*)&g_qkv[rb + 2 * DM];
            split_store(Vh + row * LQ + c4, Vl + row * LQ + c4, vv);
        }
        if (tid < 64)
            madd[tid] = mask[(size_t)b * N_ + j0 + tid] ? -1e30f : 0.0f;
        __syncthreads();

        float sacc[8][4];
        #pragma unroll
        for (int nt = 0; nt < 8; nt++)
            #pragma unroll
            for (int r = 0; r < 4; r++) sacc[nt][r] = 0.f;

        #pragma unroll
        for (int kc = 0; kc < 4; kc++) {
            int qb = qrow + kc * 16;
            uint32_t qh[4], ql[4];
            qh[0] = *(const uint32_t*)(Qh + qb);
            qh[1] = *(const uint32_t*)(Qh + qb + 8 * LQ);
            qh[2] = *(const uint32_t*)(Qh + qb + 8);
            qh[3] = *(const uint32_t*)(Qh + qb + 8 * LQ + 8);
            ql[0] = *(const uint32_t*)(Ql + qb);
            ql[1] = *(const uint32_t*)(Ql + qb + 8 * LQ);
            ql[2] = *(const uint32_t*)(Ql + qb + 8);
            ql[3] = *(const uint32_t*)(Ql + qb + 8 * LQ + 8);
            #pragma unroll
            for (int nt = 0; nt < 8; nt++) {
                int kb = (8 * nt + g) * LQ + kc * 16 + tg * 2;
                uint32_t bh[2], bl[2];
                bh[0] = *(const uint32_t*)(Kh + kb);
                bh[1] = *(const uint32_t*)(Kh + kb + 8);
                bl[0] = *(const uint32_t*)(Kl + kb);
                bl[1] = *(const uint32_t*)(Kl + kb + 8);
                MMA16816(sacc[nt], qh, bh);
                MMA16816(sacc[nt], ql, bh);
                MMA16816(sacc[nt], qh, bl);
            }
        }

        const float* bp0 = &g_bias[bias_row0 + j0];
        const float* bp1 = bp0 + 8 * N_;
        #pragma unroll
        for (int nt = 0; nt < 8; nt++) {
            int col = 8 * nt + tg * 2;
            float2 mz = *(float2*)&madd[col];
            float2 bz0 = *(const float2*)&bp0[col];
            float2 bz1 = *(const float2*)&bp1[col];
            sacc[nt][0] = fmaf(sacc[nt][0], SCALE, bz0.x) + mz.x;
            sacc[nt][1] = fmaf(sacc[nt][1], SCALE, bz0.y) + mz.y;
            sacc[nt][2] = fmaf(sacc[nt][2], SCALE, bz1.x) + mz.x;
            sacc[nt][3] = fmaf(sacc[nt][3], SCALE, bz1.y) + mz.y;
        }

        float mx0 = -INFINITY, mx1 = -INFINITY;
        #pragma unroll
        for (int nt = 0; nt < 8; nt++) {
            mx0 = fmaxf(mx0, fmaxf(sacc[nt][0], sacc[nt][1]));
            mx1 = fmaxf(mx1, fmaxf(sacc[nt][2], sacc[nt][3]));
        }
        mx0 = fmaxf(mx0, __shfl_xor_sync(0xffffffffu, mx0, 1));
        mx0 = fmaxf(mx0, __shfl_xor_sync(0xffffffffu, mx0, 2));
        mx1 = fmaxf(mx1, __shfl_xor_sync(0xffffffffu, mx1, 1));
        mx1 = fmaxf(mx1, __shfl_xor_sync(0xffffffffu, mx1, 2));

        float mn0 = fmaxf(m0r, mx0), mn1 = fmaxf(m1r, mx1);
        float a0 = exp_fast(m0r - mn0), a1 = exp_fast(m1r - mn1);
        m0r = mn0; m1r = mn1;

        float rs0 = 0.f, rs1 = 0.f;
        #pragma unroll
        for (int nt = 0; nt < 8; nt++) {
            float p0 = exp_fast(sacc[nt][0] - mn0);
            float p1 = exp_fast(sacc[nt][1] - mn0);
            float p2 = exp_fast(sacc[nt][2] - mn1);
            float p3 = exp_fast(sacc[nt][3] - mn1);
            sacc[nt][0] = p0; sacc[nt][1] = p1;
            sacc[nt][2] = p2; sacc[nt][3] = p3;
            rs0 += p0 + p1; rs1 += p2 + p3;
        }
        rs0 += __shfl_xor_sync(0xffffffffu, rs0, 1);
        rs0 += __shfl_xor_sync(0xffffffffu, rs0, 2);
        rs1 += __shfl_xor_sync(0xffffffffu, rs1, 1);
        rs1 += __shfl_xor_sync(0xffffffffu, rs1, 2);
        l0r = l0r * a0 + rs0;
        l1r = l1r * a1 + rs1;
        #pragma unroll
        for (int nt = 0; nt < 8; nt++) {
            oacc[nt][0] *= a0; oacc[nt][1] *= a0;
            oacc[nt][2] *= a1; oacc[nt][3] *= a1;
        }

        #pragma unroll
        for (int kc = 0; kc < 4; kc++) {
            uint32_t ph[4], pl[4];
            split2(sacc[2 * kc][0],     sacc[2 * kc][1],     ph[0], pl[0]);
            split2(sacc[2 * kc][2],     sacc[2 * kc][3],     ph[1], pl[1]);
            split2(sacc[2 * kc + 1][0], sacc[2 * kc + 1][1], ph[2], pl[2]);
            split2(sacc[2 * kc + 1][2], sacc[2 * kc + 1][3], ph[3], pl[3]);

            uint32_t rowoff = (uint32_t)((16 * kc + (lane & 15)) * LQ) * 2;
            #pragma unroll
            for (int ntd = 0; ntd < 8; ntd++) {
                uint32_t bh[2], bl[2];
                LDMX2T(bh[0], bh[1], vh_u32 + rowoff + ntd * 16);
                LDMX2T(bl[0], bl[1], vl_u32 + rowoff + ntd * 16);
                MMA16816(oacc[ntd], ph, bh);
                MMA16816(oacc[ntd], pl, bh);
                MMA16816(oacc[ntd], ph, bl);
            }
        }
    }

    float inv0 = 1.0f / l0r, inv1 = 1.0f / l1r;
    const size_t orow0 = ((size_t)(b * N_ + i0 + w * 16 + g)) * DM + h * DH;
    const size_t orow1 = orow0 + (size_t)8 * DM;
    #pragma unroll
    for (int nt = 0; nt < 8; nt++) {
        int col = 8 * nt + tg * 2;
        *(float2*)&g_att[orow0 + col] =
            make_float2(oacc[nt][0] * inv0, oacc[nt][1] * inv0);
        *(float2*)&g_att[orow1 + col] =
            make_float2(oacc[nt][2] * inv1, oacc[nt][3] * inv1);
    }
}

// =====================================================================
extern "C" void kernel_launch(void* const* d_in, const int* in_sizes, int n_in,
                              void* d_out, int out_size)
{
    const float* x        = (const float*)d_in[0];
    const float* coords   = (const float*)d_in[1];
    const unsigned char* mask = (const unsigned char*)d_in[2];
    const float* qkv_w    = (const float*)d_in[3];
    const float* out_w    = (const float*)d_in[4];
    const float* out_b    = (const float*)d_in[5];
    const float* alpha    = (const float*)d_in[6];
    const float* w1       = (const float*)d_in[7];
    const float* b1       = (const float*)d_in[8];
    const float* w2       = (const float*)d_in[9];
    const float* b2       = (const float*)d_in[10];
    const float* cscales  = (const float*)d_in[11];
    float* out            = (float*)d_out;

    cudaFuncSetAttribute(k_gemm_qkv_mma, cudaFuncAttributeMaxDynamicSharedMemorySize,
                         GEMM_SMEM);
    cudaFuncSetAttribute(k_gemm_out_mma, cudaFuncAttributeMaxDynamicSharedMemorySize,
                         GEMM_SMEM);
    cudaFuncSetAttribute(k_attn_mma, cudaFuncAttributeMaxDynamicSharedMemorySize,
                         ATTN_SMEM2);

    // QKV projection (mma.sync split-bf16)
    {
        dim3 grid(QKVD / 128, (B_ * N_) / 128);
        k_gemm_qkv_mma<<<grid, 256, GEMM_SMEM>>>(x, qkv_w);
    }
    // pairwise bias MLP (both layers on tensor cores)
    {
        dim3 grid(N_ / 128, N_ / 8, B_);
        k_bias_mma<<<grid, 256>>>(coords, cscales, w1, b1, w2, b2, alpha);
    }
    // tensor-core flash attention with additive bias
    {
        dim3 grid(N_ / 128, H_, B_);
        k_attn_mma<<<grid, 256, ATTN_SMEM2>>>(mask);
    }
    // output projection (mma.sync split-bf16)
    {
        dim3 grid(DM / 128, (B_ * N_) / 128);
        k_gemm_out_mma<<<grid, 256, GEMM_SMEM>>>(out_w, out_b, out);
    }
}